// round 10
// baseline (speedup 1.0000x reference)
#include <cuda_runtime.h>
#include <cuda_fp16.h>
#include <stdint.h>

#define BB 8
#define SS 1024
#define EE 1024
#define HH 16
#define M_TOT 8192
#define NELEM ((size_t)M_TOT * EE)   /* 8388608 */

// ---------------- scratch (device globals; no allocations) ----------------
__device__ __half g_Xh[NELEM], g_Xl[NELEM];
__device__ __half g_Wth[4 * 1048576], g_Wtl[4 * 1048576];  // [N][K], scaled x32
__device__ __half g_Qh[NELEM], g_Ql[NELEM];   // gate*2*0.125*log2e folded
__device__ __half g_Kh[NELEM], g_Kl[NELEM];   // gate*2 folded
__device__ __half g_Vt[NELEM];                // [(b*H+h)*64+d][s], single fp16
__device__ __half g_Oh[NELEM], g_Ol[NELEM];
__device__ float g_R[NELEM];

// ---------------- helpers ----------------
__device__ __forceinline__ void mma_f16(float* c, const uint32_t* a,
                                        uint32_t b0, uint32_t b1) {
    asm volatile(
        "mma.sync.aligned.m16n8k16.row.col.f32.f16.f16.f32 "
        "{%0,%1,%2,%3}, {%4,%5,%6,%7}, {%8,%9}, {%0,%1,%2,%3};"
        : "+f"(c[0]), "+f"(c[1]), "+f"(c[2]), "+f"(c[3])
        : "r"(a[0]), "r"(a[1]), "r"(a[2]), "r"(a[3]), "r"(b0), "r"(b1));
}

__device__ __forceinline__ void ldsm4(uint32_t* r, uint32_t addr) {
    asm volatile("ldmatrix.sync.aligned.m8n8.x4.shared.b16 {%0,%1,%2,%3}, [%4];"
                 : "=r"(r[0]), "=r"(r[1]), "=r"(r[2]), "=r"(r[3]) : "r"(addr));
}

__device__ __forceinline__ void cp16(uint32_t s, const void* g) {
    asm volatile("cp.async.cg.shared.global [%0], [%1], 16;" :: "r"(s), "l"(g));
}
#define CP_COMMIT asm volatile("cp.async.commit_group;" ::: "memory")
#define CP_WAIT(n) asm volatile("cp.async.wait_group %0;" :: "n"(n) : "memory")

__device__ __forceinline__ uint32_t smem_u32(const void* p) {
    uint32_t a;
    asm("{ .reg .u64 t; cvta.to.shared.u64 t, %1; cvt.u32.u64 %0, t; }"
        : "=r"(a) : "l"(p));
    return a;
}

__device__ __forceinline__ void split2(float x, float y, uint32_t& h, uint32_t& l) {
    __half2 hh = __floats2half2_rn(x, y);
    __half2 ll = __floats2half2_rn(x - __low2float(hh), y - __high2float(hh));
    h = *(uint32_t*)&hh;
    l = *(uint32_t*)&ll;
}

__device__ __forceinline__ uint32_t packh2(float x, float y) {
    __half2 hh = __floats2half2_rn(x, y);
    return *(uint32_t*)&hh;
}

__device__ __forceinline__ void split1(float x, __half& h, __half& l) {
    h = __float2half_rn(x);
    l = __float2half_rn(x - __half2float(h));
}

// ---------------- prep: split X into fp16 hi/lo ----------------
__global__ __launch_bounds__(256) void prep_x_kernel(const float* __restrict__ X)
{
    size_t i = ((size_t)blockIdx.x * 256 + threadIdx.x) * 4;
    float4 v = *(const float4*)(X + i);
    uint32_t h01, l01, h23, l23;
    split2(v.x, v.y, h01, l01);
    split2(v.z, v.w, h23, l23);
    *(uint32_t*)(g_Xh + i)     = h01;
    *(uint32_t*)(g_Xh + i + 2) = h23;
    *(uint32_t*)(g_Xl + i)     = l01;
    *(uint32_t*)(g_Xl + i + 2) = l23;
}

// ---------------- prep: weights x32 -> K-major fp16 hi/lo ----------------
__global__ __launch_bounds__(256) void prep_w_kernel(
    const float* __restrict__ Wq, const float* __restrict__ Wk,
    const float* __restrict__ Wv, const float* __restrict__ Wo)
{
    const int which = blockIdx.z;
    const float* W = (which == 0) ? Wq : (which == 1) ? Wk : (which == 2) ? Wv : Wo;
    __half* Oh = g_Wth + (size_t)which * 1048576;
    __half* Ol = g_Wtl + (size_t)which * 1048576;

    __shared__ float tile[32][33];
    const int tx = threadIdx.x, ty = threadIdx.y;
    const int n0 = blockIdx.x * 32, k0 = blockIdx.y * 32;

    if (which < 3) {
#pragma unroll
        for (int i = 0; i < 4; i++)
            tile[ty + 8 * i][tx] = W[(size_t)(k0 + ty + 8 * i) * EE + n0 + tx];
        __syncthreads();
#pragma unroll
        for (int i = 0; i < 4; i++) {
            float v = tile[tx][ty + 8 * i] * 32.0f;
            __half h, l;
            split1(v, h, l);
            size_t o = (size_t)(n0 + ty + 8 * i) * EE + k0 + tx;
            Oh[o] = h; Ol[o] = l;
        }
    } else {
#pragma unroll
        for (int i = 0; i < 4; i++) {
            size_t o = (size_t)(n0 + ty + 8 * i) * EE + k0 + tx;
            float v = W[o] * 32.0f;
            __half h, l;
            split1(v, h, l);
            Oh[o] = h; Ol[o] = l;
        }
    }
}

// ---------------- GEMM: 64x64 warp tiles, CTA 128x128, 2 CTAs/SM ------------
// modes 0,1 (Q,K): 3-term. modes 2,3 (V,out-proj): 2-term (B_lo dropped).
#define GROW 80                            /* 64B data + 16 pad */
#define GTILE (128 * GROW)                 /* 10240 */
#define GSTAGE (4 * GTILE)                 /* Ah, Al, Bh, Bl = 40960 */
#define GEMM_SMEM (2 * GSTAGE)             /* 81920 */
#define INV32 0.03125f

__global__ __launch_bounds__(128, 2) void gemm_kernel(
    const float* __restrict__ AuxQ, const float* __restrict__ AuxK,
    const float* __restrict__ AuxX, int modeBase)
{
    extern __shared__ char smb[];
    const uint32_t sbase = smem_u32(smb);

    const int mode = modeBase + blockIdx.z;
    const bool threeTerm = (mode <= 1);
    const __half* Ahp = (mode == 3) ? g_Oh : g_Xh;
    const __half* Alp = (mode == 3) ? g_Ol : g_Xl;
    const __half* Bhp = g_Wth + (size_t)mode * 1048576;
    const __half* Blp = g_Wtl + (size_t)mode * 1048576;

    const int tid = threadIdx.x;
    const int wid = tid >> 5;
    const int lane = tid & 31;
    const int g = lane >> 2;
    const int tig = lane & 3;
    const int wm = wid >> 1;
    const int wn = wid & 1;
    const int colBase = blockIdx.x * 128;
    const int rowBase = blockIdx.y * 128;

    float c[4][8][4];
#pragma unroll
    for (int mt = 0; mt < 4; mt++)
#pragma unroll
        for (int nt = 0; nt < 8; nt++)
#pragma unroll
            for (int r = 0; r < 4; r++) c[mt][nt][r] = 0.f;

    const uint32_t aLane = (uint32_t)(wm * 64 + (lane & 7) + ((lane >> 3) & 1) * 8) * GROW
                         + ((lane >> 4) & 1) * 16;
    const uint32_t bLane = (uint32_t)(wn * 64 + (lane & 7) + ((lane >> 4) & 1) * 8) * GROW
                         + ((lane >> 3) & 1) * 16;

    auto issue = [&](int kt, int stage) {
        uint32_t sb = sbase + stage * GSTAGE;
#pragma unroll
        for (int i = 0; i < 4; i++) {
            int ch = tid + i * 128;
            int r = ch >> 2;
            int cb = (ch & 3) * 16;
            int c8 = (ch & 3) * 8;
            size_t ao = (size_t)(rowBase + r) * EE + kt * 32 + c8;
            uint32_t off = r * GROW + cb;
            cp16(sb + off,         Ahp + ao);
            cp16(sb + GTILE + off, Alp + ao);
        }
#pragma unroll
        for (int i = 0; i < 4; i++) {
            int ch = tid + i * 128;
            int r = ch >> 2;
            int cb = (ch & 3) * 16;
            int c8 = (ch & 3) * 8;
            size_t bo = (size_t)(colBase + r) * EE + kt * 32 + c8;
            uint32_t off = r * GROW + cb;
            cp16(sb + 2 * GTILE + off, Bhp + bo);
            if (threeTerm)
                cp16(sb + 3 * GTILE + off, Blp + bo);
        }
        CP_COMMIT;
    };

    issue(0, 0);

    for (int kt = 0; kt < 32; kt++) {
        CP_WAIT(0);
        __syncthreads();
        if (kt + 1 < 32) issue(kt + 1, (kt + 1) & 1);

        const uint32_t sb = sbase + (kt & 1) * GSTAGE;
        const uint32_t aOff = sb + aLane;
        const uint32_t bOff = sb + 2 * GTILE + bLane;

#pragma unroll
        for (int ks = 0; ks < 2; ks++) {
            uint32_t ah[4][4], al[4][4], bh[4][4];
#pragma unroll
            for (int mt = 0; mt < 4; mt++) {
                ldsm4(ah[mt], aOff + mt * 16 * GROW + ks * 32);
                ldsm4(al[mt], aOff + GTILE + mt * 16 * GROW + ks * 32);
            }
#pragma unroll
            for (int p = 0; p < 4; p++)
                ldsm4(bh[p], bOff + p * 16 * GROW + ks * 32);
#pragma unroll
            for (int p = 0; p < 4; p++)
#pragma unroll
                for (int mt = 0; mt < 4; mt++) {
                    mma_f16(c[mt][2 * p],     ah[mt], bh[p][0], bh[p][1]);
                    mma_f16(c[mt][2 * p + 1], ah[mt], bh[p][2], bh[p][3]);
                }
#pragma unroll
            for (int p = 0; p < 4; p++)
#pragma unroll
                for (int mt = 0; mt < 4; mt++) {
                    mma_f16(c[mt][2 * p],     al[mt], bh[p][0], bh[p][1]);
                    mma_f16(c[mt][2 * p + 1], al[mt], bh[p][2], bh[p][3]);
                }
            if (threeTerm) {
                uint32_t bl[4][4];
#pragma unroll
                for (int p = 0; p < 4; p++)
                    ldsm4(bl[p], bOff + GTILE + p * 16 * GROW + ks * 32);
#pragma unroll
                for (int p = 0; p < 4; p++)
#pragma unroll
                    for (int mt = 0; mt < 4; mt++) {
                        mma_f16(c[mt][2 * p],     ah[mt], bl[p][0], bl[p][1]);
                        mma_f16(c[mt][2 * p + 1], ah[mt], bl[p][2], bl[p][3]);
                    }
            }
        }
    }

    // ---- epilogues (fold 1/32 from weight scaling) ----
    const int batch = rowBase / SS;
    if (mode <= 1) {
        __half* Oh = (mode == 0) ? g_Qh : g_Kh;
        __half* Ol = (mode == 0) ? g_Ql : g_Kl;
        const float sc = ((mode == 0) ? 0.25f * 1.44269504089f : 2.0f) * INV32;
        const float* Aux = (mode == 0) ? AuxQ : AuxK;
#pragma unroll
        for (int mt = 0; mt < 4; mt++) {
            size_t row0 = (size_t)rowBase + wm * 64 + mt * 16 + g;
#pragma unroll
            for (int nt = 0; nt < 8; nt++) {
                int col = colBase + wn * 64 + nt * 8 + 2 * tig;
                float2 gv = *(const float2*)(Aux + (size_t)batch * EE + col);
                float gx = gv.x * sc, gy = gv.y * sc;
                uint32_t h, l;
                split2(c[mt][nt][0] * gx, c[mt][nt][1] * gy, h, l);
                *(uint32_t*)(Oh + row0 * EE + col) = h;
                *(uint32_t*)(Ol + row0 * EE + col) = l;
                split2(c[mt][nt][2] * gx, c[mt][nt][3] * gy, h, l);
                *(uint32_t*)(Oh + (row0 + 8) * EE + col) = h;
                *(uint32_t*)(Ol + (row0 + 8) * EE + col) = l;
            }
        }
    } else if (mode == 2) {
#pragma unroll
        for (int mt = 0; mt < 4; mt++) {
            int row0 = rowBase + wm * 64 + mt * 16 + g;
            int s = row0 - batch * SS;
#pragma unroll
            for (int nt = 0; nt < 8; nt++) {
                int col = colBase + wn * 64 + nt * 8 + 2 * tig;
                int hh = col >> 6, d = col & 63;
                size_t vb = ((size_t)(batch * HH + hh) * 64 + d) * SS + s;
                g_Vt[vb]          = __float2half_rn(c[mt][nt][0] * INV32);
                g_Vt[vb + SS]     = __float2half_rn(c[mt][nt][1] * INV32);
                g_Vt[vb + 8]      = __float2half_rn(c[mt][nt][2] * INV32);
                g_Vt[vb + SS + 8] = __float2half_rn(c[mt][nt][3] * INV32);
            }
        }
    } else {
#pragma unroll
        for (int mt = 0; mt < 4; mt++) {
            size_t row0 = (size_t)rowBase + wm * 64 + mt * 16 + g;
#pragma unroll
            for (int nt = 0; nt < 8; nt++) {
                int col = colBase + wn * 64 + nt * 8 + 2 * tig;
                float2 x0 = *(const float2*)(AuxX + row0 * EE + col);
                float2 x1 = *(const float2*)(AuxX + (row0 + 8) * EE + col);
                *(float2*)(g_R + row0 * EE + col) =
                    make_float2(c[mt][nt][0] * INV32 + x0.x, c[mt][nt][1] * INV32 + x0.y);
                *(float2*)(g_R + (row0 + 8) * EE + col) =
                    make_float2(c[mt][nt][2] * INV32 + x1.x, c[mt][nt][3] * INV32 + x1.y);
            }
        }
    }
}

// ---- flash attention: fp16, PV single-term, 3-stage ring, pipelined softmax ----
#define AROW 144
#define ATILE (64 * AROW)                  /* 9216 */
#define ABUF (3 * ATILE)                   /* Kh, Kl, V = 27648 */
#define ATTN_SMEM (3 * ABUF)               /* 82944: 3-stage ring */

__global__ __launch_bounds__(128, 2) void attn_kernel()
{
    extern __shared__ char smb[];
    const uint32_t sbase = smem_u32(smb);

    const int qt = blockIdx.x;     // 0..15 (64 q rows each)
    const int h  = blockIdx.y;
    const int b  = blockIdx.z;
    const int tid = threadIdx.x;
    const int wid = tid >> 5;      // 0..3
    const int lane = tid & 31;
    const int g = lane >> 2;
    const int tig = lane & 3;

    const size_t kbase0 = ((size_t)b * SS) * EE + h * 64;
    const size_t vbase0 = ((size_t)(b * HH + h) * 64) * SS;

    auto issue = [&](int kt, int stage) {
        uint32_t sb = sbase + stage * ABUF;
#pragma unroll
        for (int i = 0; i < 4; i++) {
            int ch = tid + i * 128;        // 0..511
            int r = ch >> 3;               // 0..63
            int cb = (ch & 7) * 16;
            int c8 = (ch & 7) * 8;
            size_t ko = kbase0 + (size_t)(kt * 64 + r) * EE + c8;
            size_t vo = vbase0 + (size_t)r * SS + kt * 64 + c8;
            uint32_t off = r * AROW + cb;
            cp16(sb + off,             g_Kh + ko);
            cp16(sb + ATILE + off,     g_Kl + ko);
            cp16(sb + 2 * ATILE + off, g_Vt + vo);
        }
        CP_COMMIT;
    };

    issue(0, 0);
    issue(1, 1);

    // ---- Q fragments (held all kernel; log2e pre-folded) ----
    uint32_t qh[4][4], ql[4][4];
    {
        size_t rg = (size_t)(b * SS + qt * 64 + wid * 16 + g);
        const __half* ph = g_Qh + rg * EE + h * 64;
        const __half* pl = g_Ql + rg * EE + h * 64;
#pragma unroll
        for (int ks = 0; ks < 4; ks++) {
            int c0 = ks * 16 + 2 * tig;
            qh[ks][0] = *(const uint32_t*)(ph + c0);
            qh[ks][1] = *(const uint32_t*)(ph + 8 * EE + c0);
            qh[ks][2] = *(const uint32_t*)(ph + c0 + 8);
            qh[ks][3] = *(const uint32_t*)(ph + 8 * EE + c0 + 8);
            ql[ks][0] = *(const uint32_t*)(pl + c0);
            ql[ks][1] = *(const uint32_t*)(pl + 8 * EE + c0);
            ql[ks][2] = *(const uint32_t*)(pl + c0 + 8);
            ql[ks][3] = *(const uint32_t*)(pl + 8 * EE + c0 + 8);
        }
    }

    float acc[8][4];
#pragma unroll
    for (int j = 0; j < 8; j++)
#pragma unroll
        for (int r = 0; r < 4; r++) acc[j][r] = 0.f;
    float m0 = -1e30f, m1 = -1e30f, l0 = 0.f, l1 = 0.f;

    const uint32_t fLane = (uint32_t)((lane & 7) + ((lane >> 4) & 1) * 8) * AROW
                         + ((lane >> 3) & 1) * 16;

    // scores of a tile from its stage into cD
    auto scores = [&](int stage, float (*cD)[4]) {
        const uint32_t kOff = sbase + stage * ABUF + fLane;
#pragma unroll
        for (int j = 0; j < 8; j++)
#pragma unroll
            for (int r = 0; r < 4; r++) cD[j][r] = 0.f;
#pragma unroll
        for (int ks = 0; ks < 4; ks++) {
            uint32_t bh[4][4], bl[4][4];
#pragma unroll
            for (int p = 0; p < 4; p++) {
                ldsm4(bh[p], kOff + p * 16 * AROW + ks * 32);
                ldsm4(bl[p], kOff + ATILE + p * 16 * AROW + ks * 32);
            }
#pragma unroll
            for (int p = 0; p < 4; p++) {
                mma_f16(cD[2 * p],     qh[ks], bh[p][0], bh[p][1]);
                mma_f16(cD[2 * p + 1], qh[ks], bh[p][2], bh[p][3]);
            }
#pragma unroll
            for (int p = 0; p < 4; p++) {
                mma_f16(cD[2 * p],     qh[ks], bl[p][0], bl[p][1]);
                mma_f16(cD[2 * p + 1], qh[ks], bl[p][2], bl[p][3]);
            }
#pragma unroll
            for (int p = 0; p < 4; p++) {
                mma_f16(cD[2 * p],     ql[ks], bh[p][0], bh[p][1]);
                mma_f16(cD[2 * p + 1], ql[ks], bh[p][2], bh[p][3]);
            }
        }
    };

    float c_cur[8][4], c_nxt[8][4];

    // prologue: tile 0 ready (g1 may still be in flight), scores(0)
    CP_WAIT(1);
    __syncthreads();
    scores(0, c_cur);

    for (int kt = 0; kt < 16; kt++) {
        // tile kt+1 ready; all warps past PV(kt-1) and scores(kt)
        CP_WAIT(0);
        __syncthreads();
        if (kt + 2 < 16) issue(kt + 2, (kt + 2) % 3);
        // issue next tile's score MMAs first — tensor work to overlap softmax
        if (kt < 15) scores((kt + 1) % 3, c_nxt);

        // ---- online softmax (exp2 domain) on c_cur ----
        float mx0 = -1e30f, mx1 = -1e30f;
#pragma unroll
        for (int j = 0; j < 8; j++) {
            mx0 = fmaxf(mx0, fmaxf(c_cur[j][0], c_cur[j][1]));
            mx1 = fmaxf(mx1, fmaxf(c_cur[j][2], c_cur[j][3]));
        }
        mx0 = fmaxf(mx0, __shfl_xor_sync(0xffffffffu, mx0, 1));
        mx0 = fmaxf(mx0, __shfl_xor_sync(0xffffffffu, mx0, 2));
        mx1 = fmaxf(mx1, __shfl_xor_sync(0xffffffffu, mx1, 1));
        mx1 = fmaxf(mx1, __shfl_xor_sync(0xffffffffu, mx1, 2));
        float mn0 = fmaxf(m0, mx0), mn1 = fmaxf(m1, mx1);
        float cr0 = exp2f(m0 - mn0), cr1 = exp2f(m1 - mn1);
        float s0 = 0.f, s1 = 0.f;
#pragma unroll
        for (int j = 0; j < 8; j++) {
            c_cur[j][0] = exp2f(c_cur[j][0] - mn0);
            c_cur[j][1] = exp2f(c_cur[j][1] - mn0);
            c_cur[j][2] = exp2f(c_cur[j][2] - mn1);
            c_cur[j][3] = exp2f(c_cur[j][3] - mn1);
            s0 += c_cur[j][0] + c_cur[j][1];
            s1 += c_cur[j][2] + c_cur[j][3];
        }
        s0 += __shfl_xor_sync(0xffffffffu, s0, 1);
        s0 += __shfl_xor_sync(0xffffffffu, s0, 2);
        s1 += __shfl_xor_sync(0xffffffffu, s1, 1);
        s1 += __shfl_xor_sync(0xffffffffu, s1, 2);
        l0 = l0 * cr0 + s0;
        l1 = l1 * cr1 + s1;
        m0 = mn0; m1 = mn1;
#pragma unroll
        for (int j = 0; j < 8; j++) {
            acc[j][0] *= cr0; acc[j][1] *= cr0;
            acc[j][2] *= cr1; acc[j][3] *= cr1;
        }

        // ---- PV: single term, P and V fp16, from stage kt%3 ----
        const uint32_t vOff = sbase + (kt % 3) * ABUF + 2 * ATILE + fLane;
#pragma unroll
        for (int ks = 0; ks < 4; ks++) {
            uint32_t ph[4];
            ph[0] = packh2(c_cur[2 * ks][0],     c_cur[2 * ks][1]);
            ph[1] = packh2(c_cur[2 * ks][2],     c_cur[2 * ks][3]);
            ph[2] = packh2(c_cur[2 * ks + 1][0], c_cur[2 * ks + 1][1]);
            ph[3] = packh2(c_cur[2 * ks + 1][2], c_cur[2 * ks + 1][3]);
            uint32_t vh[4][4];
#pragma unroll
            for (int p = 0; p < 4; p++)
                ldsm4(vh[p], vOff + p * 16 * AROW + ks * 32);
#pragma unroll
            for (int p = 0; p < 4; p++) {
                mma_f16(acc[2 * p],     ph, vh[p][0], vh[p][1]);
                mma_f16(acc[2 * p + 1], ph, vh[p][2], vh[p][3]);
            }
        }

        // rotate score buffers
        if (kt < 15) {
#pragma unroll
            for (int j = 0; j < 8; j++)
#pragma unroll
                for (int r = 0; r < 4; r++) c_cur[j][r] = c_nxt[j][r];
        }
    }

    // ---- epilogue: O = acc/l, write fp16 hi/lo ----
    float i0 = 1.f / l0, i1 = 1.f / l1;
    size_t rg = (size_t)(b * SS + qt * 64 + wid * 16 + g);
#pragma unroll
    for (int j = 0; j < 8; j++) {
        int col = h * 64 + j * 8 + 2 * tig;
        uint32_t hh, ll;
        split2(acc[j][0] * i0, acc[j][1] * i0, hh, ll);
        *(uint32_t*)(g_Oh + rg * EE + col) = hh;
        *(uint32_t*)(g_Ol + rg * EE + col) = ll;
        split2(acc[j][2] * i1, acc[j][3] * i1, hh, ll);
        *(uint32_t*)(g_Oh + (rg + 8) * EE + col) = hh;
        *(uint32_t*)(g_Ol + (rg + 8) * EE + col) = ll;
    }
}

// ---------------- LayerNorm ----------------
__global__ __launch_bounds__(256) void ln_kernel(
    const float* __restrict__ gamma, const float* __restrict__ beta,
    float* __restrict__ out)
{
    const int row = blockIdx.x;
    const int tid = threadIdx.x;
    const float4 v = *(const float4*)(g_R + (size_t)row * EE + tid * 4);

    float s1 = v.x + v.y + v.z + v.w;
    float s2 = v.x * v.x + v.y * v.y + v.z * v.z + v.w * v.w;

    __shared__ float sh1[8], sh2[8];
#pragma unroll
    for (int off = 16; off > 0; off >>= 1) {
        s1 += __shfl_xor_sync(0xffffffffu, s1, off);
        s2 += __shfl_xor_sync(0xffffffffu, s2, off);
    }
    const int warp = tid >> 5;
    if ((tid & 31) == 0) { sh1[warp] = s1; sh2[warp] = s2; }
    __syncthreads();
    float t1 = 0.f, t2 = 0.f;
#pragma unroll
    for (int w = 0; w < 8; w++) { t1 += sh1[w]; t2 += sh2[w]; }

    const float mean = t1 * (1.0f / EE);
    const float var  = t2 * (1.0f / EE) - mean * mean;
    const float inv  = rsqrtf(var + 1e-6f);

    const float4 gmv = *(const float4*)(gamma + tid * 4);
    const float4 btv = *(const float4*)(beta + tid * 4);
    float4 o;
    o.x = (v.x - mean) * inv * gmv.x + btv.x;
    o.y = (v.y - mean) * inv * gmv.y + btv.y;
    o.z = (v.z - mean) * inv * gmv.z + btv.z;
    o.w = (v.w - mean) * inv * gmv.w + btv.w;
    *(float4*)(out + (size_t)row * EE + tid * 4) = o;
}

// ---------------------------------------------------------------------------
extern "C" void kernel_launch(void* const* d_in, const int* in_sizes, int n_in,
                              void* d_out, int out_size)
{
    const float* X     = (const float*)d_in[0];
    const float* gQ    = (const float*)d_in[1];
    const float* gK    = (const float*)d_in[2];
    const float* Wq    = (const float*)d_in[3];
    const float* Wk    = (const float*)d_in[4];
    const float* Wv    = (const float*)d_in[5];
    const float* Wo    = (const float*)d_in[6];
    const float* gamma = (const float*)d_in[7];
    const float* beta  = (const float*)d_in[8];
    float* out = (float*)d_out;

    cudaFuncSetAttribute(gemm_kernel,
                         cudaFuncAttributeMaxDynamicSharedMemorySize, GEMM_SMEM);
    cudaFuncSetAttribute(attn_kernel,
                         cudaFuncAttributeMaxDynamicSharedMemorySize, ATTN_SMEM);

    prep_x_kernel<<<NELEM / 1024, 256>>>(X);
    prep_w_kernel<<<dim3(32, 32, 4), dim3(32, 8)>>>(Wq, Wk, Wv, Wo);

    gemm_kernel<<<dim3(8, 64, 3), 128, GEMM_SMEM>>>(gQ, gK, X, 0);

    attn_kernel<<<dim3(16, HH, BB), 128, ATTN_SMEM>>>();

    gemm_kernel<<<dim3(8, 64, 1), 128, GEMM_SMEM>>>(gQ, gK, X, 3);
    ln_kernel<<<M_TOT, 256>>>(gamma, beta, out);
}

// round 11
// speedup vs baseline: 1.1610x; 1.1610x over previous
#include <cuda_runtime.h>
#include <cuda_fp16.h>
#include <stdint.h>

#define BB 8
#define SS 1024
#define EE 1024
#define HH 16
#define M_TOT 8192
#define NELEM ((size_t)M_TOT * EE)   /* 8388608 */

// ---------------- scratch (device globals; no allocations) ----------------
__device__ __half g_Xh[NELEM], g_Xl[NELEM];
__device__ __half g_Wth[4 * 1048576], g_Wtl[4 * 1048576];  // [N][K], scaled x32
__device__ __half g_Qh[NELEM], g_Ql[NELEM];   // gate*2*0.125*log2e folded
__device__ __half g_Kh[NELEM], g_Kl[NELEM];   // gate*2 folded
__device__ __half g_Vt[NELEM];                // [(b*H+h)*64+d][s], single fp16
__device__ __half g_Oh[NELEM], g_Ol[NELEM];
__device__ float g_R[NELEM];

// ---------------- helpers ----------------
__device__ __forceinline__ void mma_f16(float* c, const uint32_t* a,
                                        uint32_t b0, uint32_t b1) {
    asm volatile(
        "mma.sync.aligned.m16n8k16.row.col.f32.f16.f16.f32 "
        "{%0,%1,%2,%3}, {%4,%5,%6,%7}, {%8,%9}, {%0,%1,%2,%3};"
        : "+f"(c[0]), "+f"(c[1]), "+f"(c[2]), "+f"(c[3])
        : "r"(a[0]), "r"(a[1]), "r"(a[2]), "r"(a[3]), "r"(b0), "r"(b1));
}

__device__ __forceinline__ void ldsm4(uint32_t* r, uint32_t addr) {
    asm volatile("ldmatrix.sync.aligned.m8n8.x4.shared.b16 {%0,%1,%2,%3}, [%4];"
                 : "=r"(r[0]), "=r"(r[1]), "=r"(r[2]), "=r"(r[3]) : "r"(addr));
}

__device__ __forceinline__ void cp16(uint32_t s, const void* g) {
    asm volatile("cp.async.cg.shared.global [%0], [%1], 16;" :: "r"(s), "l"(g));
}
#define CP_COMMIT asm volatile("cp.async.commit_group;" ::: "memory")
#define CP_WAIT(n) asm volatile("cp.async.wait_group %0;" :: "n"(n) : "memory")

__device__ __forceinline__ uint32_t smem_u32(const void* p) {
    uint32_t a;
    asm("{ .reg .u64 t; cvta.to.shared.u64 t, %1; cvt.u32.u64 %0, t; }"
        : "=r"(a) : "l"(p));
    return a;
}

__device__ __forceinline__ void split2(float x, float y, uint32_t& h, uint32_t& l) {
    __half2 hh = __floats2half2_rn(x, y);
    __half2 ll = __floats2half2_rn(x - __low2float(hh), y - __high2float(hh));
    h = *(uint32_t*)&hh;
    l = *(uint32_t*)&ll;
}

__device__ __forceinline__ uint32_t packh2(float x, float y) {
    __half2 hh = __floats2half2_rn(x, y);
    return *(uint32_t*)&hh;
}

__device__ __forceinline__ void split1(float x, __half& h, __half& l) {
    h = __float2half_rn(x);
    l = __float2half_rn(x - __half2float(h));
}

// ---------------- prep: split X into fp16 hi/lo ----------------
__global__ __launch_bounds__(256) void prep_x_kernel(const float* __restrict__ X)
{
    size_t i = ((size_t)blockIdx.x * 256 + threadIdx.x) * 4;
    float4 v = *(const float4*)(X + i);
    uint32_t h01, l01, h23, l23;
    split2(v.x, v.y, h01, l01);
    split2(v.z, v.w, h23, l23);
    *(uint32_t*)(g_Xh + i)     = h01;
    *(uint32_t*)(g_Xh + i + 2) = h23;
    *(uint32_t*)(g_Xl + i)     = l01;
    *(uint32_t*)(g_Xl + i + 2) = l23;
}

// ---------------- prep: weights x32 -> K-major fp16 hi/lo ----------------
__global__ __launch_bounds__(256) void prep_w_kernel(
    const float* __restrict__ Wq, const float* __restrict__ Wk,
    const float* __restrict__ Wv, const float* __restrict__ Wo)
{
    const int which = blockIdx.z;
    const float* W = (which == 0) ? Wq : (which == 1) ? Wk : (which == 2) ? Wv : Wo;
    __half* Oh = g_Wth + (size_t)which * 1048576;
    __half* Ol = g_Wtl + (size_t)which * 1048576;

    __shared__ float tile[32][33];
    const int tx = threadIdx.x, ty = threadIdx.y;
    const int n0 = blockIdx.x * 32, k0 = blockIdx.y * 32;

    if (which < 3) {
#pragma unroll
        for (int i = 0; i < 4; i++)
            tile[ty + 8 * i][tx] = W[(size_t)(k0 + ty + 8 * i) * EE + n0 + tx];
        __syncthreads();
#pragma unroll
        for (int i = 0; i < 4; i++) {
            float v = tile[tx][ty + 8 * i] * 32.0f;
            __half h, l;
            split1(v, h, l);
            size_t o = (size_t)(n0 + ty + 8 * i) * EE + k0 + tx;
            Oh[o] = h; Ol[o] = l;
        }
    } else {
#pragma unroll
        for (int i = 0; i < 4; i++) {
            size_t o = (size_t)(n0 + ty + 8 * i) * EE + k0 + tx;
            float v = W[o] * 32.0f;
            __half h, l;
            split1(v, h, l);
            Oh[o] = h; Ol[o] = l;
        }
    }
}

// ---------------- GEMM: 64x64 warp tiles, CTA 128x128, 2 CTAs/SM ------------
// modes 0,1 (Q,K): 3-term. modes 2,3 (V,out-proj): 1-term (Ah*Bh only).
#define GROW 80                            /* 64B data + 16 pad */
#define GTILE (128 * GROW)                 /* 10240 */
#define GSTAGE (4 * GTILE)                 /* Ah, Al, Bh, Bl = 40960 */
#define GEMM_SMEM (2 * GSTAGE)             /* 81920 */
#define INV32 0.03125f

__global__ __launch_bounds__(128, 2) void gemm_kernel(
    const float* __restrict__ AuxQ, const float* __restrict__ AuxK,
    const float* __restrict__ AuxX, int modeBase)
{
    extern __shared__ char smb[];
    const uint32_t sbase = smem_u32(smb);

    const int mode = modeBase + blockIdx.z;
    const bool threeTerm = (mode <= 1);
    const __half* Ahp = (mode == 3) ? g_Oh : g_Xh;
    const __half* Alp = (mode == 3) ? g_Ol : g_Xl;
    const __half* Bhp = g_Wth + (size_t)mode * 1048576;
    const __half* Blp = g_Wtl + (size_t)mode * 1048576;

    const int tid = threadIdx.x;
    const int wid = tid >> 5;
    const int lane = tid & 31;
    const int g = lane >> 2;
    const int tig = lane & 3;
    const int wm = wid >> 1;
    const int wn = wid & 1;
    const int colBase = blockIdx.x * 128;
    const int rowBase = blockIdx.y * 128;

    float c[4][8][4];
#pragma unroll
    for (int mt = 0; mt < 4; mt++)
#pragma unroll
        for (int nt = 0; nt < 8; nt++)
#pragma unroll
            for (int r = 0; r < 4; r++) c[mt][nt][r] = 0.f;

    const uint32_t aLane = (uint32_t)(wm * 64 + (lane & 7) + ((lane >> 3) & 1) * 8) * GROW
                         + ((lane >> 4) & 1) * 16;
    const uint32_t bLane = (uint32_t)(wn * 64 + (lane & 7) + ((lane >> 4) & 1) * 8) * GROW
                         + ((lane >> 3) & 1) * 16;

    auto issue = [&](int kt, int stage) {
        uint32_t sb = sbase + stage * GSTAGE;
#pragma unroll
        for (int i = 0; i < 4; i++) {
            int ch = tid + i * 128;
            int r = ch >> 2;
            int cb = (ch & 3) * 16;
            int c8 = (ch & 3) * 8;
            size_t ao = (size_t)(rowBase + r) * EE + kt * 32 + c8;
            uint32_t off = r * GROW + cb;
            cp16(sb + off, Ahp + ao);
            if (threeTerm)
                cp16(sb + GTILE + off, Alp + ao);
        }
#pragma unroll
        for (int i = 0; i < 4; i++) {
            int ch = tid + i * 128;
            int r = ch >> 2;
            int cb = (ch & 3) * 16;
            int c8 = (ch & 3) * 8;
            size_t bo = (size_t)(colBase + r) * EE + kt * 32 + c8;
            uint32_t off = r * GROW + cb;
            cp16(sb + 2 * GTILE + off, Bhp + bo);
            if (threeTerm)
                cp16(sb + 3 * GTILE + off, Blp + bo);
        }
        CP_COMMIT;
    };

    issue(0, 0);

    for (int kt = 0; kt < 32; kt++) {
        CP_WAIT(0);
        __syncthreads();
        if (kt + 1 < 32) issue(kt + 1, (kt + 1) & 1);

        const uint32_t sb = sbase + (kt & 1) * GSTAGE;
        const uint32_t aOff = sb + aLane;
        const uint32_t bOff = sb + 2 * GTILE + bLane;

#pragma unroll
        for (int ks = 0; ks < 2; ks++) {
            uint32_t ah[4][4], bh[4][4];
#pragma unroll
            for (int mt = 0; mt < 4; mt++)
                ldsm4(ah[mt], aOff + mt * 16 * GROW + ks * 32);
#pragma unroll
            for (int p = 0; p < 4; p++)
                ldsm4(bh[p], bOff + p * 16 * GROW + ks * 32);
            // pass 1: Ah*Bh — always
#pragma unroll
            for (int p = 0; p < 4; p++)
#pragma unroll
                for (int mt = 0; mt < 4; mt++) {
                    mma_f16(c[mt][2 * p],     ah[mt], bh[p][0], bh[p][1]);
                    mma_f16(c[mt][2 * p + 1], ah[mt], bh[p][2], bh[p][3]);
                }
            if (threeTerm) {
                // pass 2: Al*Bh
                uint32_t al[4][4];
#pragma unroll
                for (int mt = 0; mt < 4; mt++)
                    ldsm4(al[mt], aOff + GTILE + mt * 16 * GROW + ks * 32);
#pragma unroll
                for (int p = 0; p < 4; p++)
#pragma unroll
                    for (int mt = 0; mt < 4; mt++) {
                        mma_f16(c[mt][2 * p],     al[mt], bh[p][0], bh[p][1]);
                        mma_f16(c[mt][2 * p + 1], al[mt], bh[p][2], bh[p][3]);
                    }
                // pass 3: Ah*Bl
                uint32_t bl[4][4];
#pragma unroll
                for (int p = 0; p < 4; p++)
                    ldsm4(bl[p], bOff + GTILE + p * 16 * GROW + ks * 32);
#pragma unroll
                for (int p = 0; p < 4; p++)
#pragma unroll
                    for (int mt = 0; mt < 4; mt++) {
                        mma_f16(c[mt][2 * p],     ah[mt], bl[p][0], bl[p][1]);
                        mma_f16(c[mt][2 * p + 1], ah[mt], bl[p][2], bl[p][3]);
                    }
            }
        }
    }

    // ---- epilogues (fold 1/32 from weight scaling) ----
    const int batch = rowBase / SS;
    if (mode <= 1) {
        __half* Oh = (mode == 0) ? g_Qh : g_Kh;
        __half* Ol = (mode == 0) ? g_Ql : g_Kl;
        const float sc = ((mode == 0) ? 0.25f * 1.44269504089f : 2.0f) * INV32;
        const float* Aux = (mode == 0) ? AuxQ : AuxK;
#pragma unroll
        for (int mt = 0; mt < 4; mt++) {
            size_t row0 = (size_t)rowBase + wm * 64 + mt * 16 + g;
#pragma unroll
            for (int nt = 0; nt < 8; nt++) {
                int col = colBase + wn * 64 + nt * 8 + 2 * tig;
                float2 gv = *(const float2*)(Aux + (size_t)batch * EE + col);
                float gx = gv.x * sc, gy = gv.y * sc;
                uint32_t h, l;
                split2(c[mt][nt][0] * gx, c[mt][nt][1] * gy, h, l);
                *(uint32_t*)(Oh + row0 * EE + col) = h;
                *(uint32_t*)(Ol + row0 * EE + col) = l;
                split2(c[mt][nt][2] * gx, c[mt][nt][3] * gy, h, l);
                *(uint32_t*)(Oh + (row0 + 8) * EE + col) = h;
                *(uint32_t*)(Ol + (row0 + 8) * EE + col) = l;
            }
        }
    } else if (mode == 2) {
#pragma unroll
        for (int mt = 0; mt < 4; mt++) {
            int row0 = rowBase + wm * 64 + mt * 16 + g;
            int s = row0 - batch * SS;
#pragma unroll
            for (int nt = 0; nt < 8; nt++) {
                int col = colBase + wn * 64 + nt * 8 + 2 * tig;
                int hh = col >> 6, d = col & 63;
                size_t vb = ((size_t)(batch * HH + hh) * 64 + d) * SS + s;
                g_Vt[vb]          = __float2half_rn(c[mt][nt][0] * INV32);
                g_Vt[vb + SS]     = __float2half_rn(c[mt][nt][1] * INV32);
                g_Vt[vb + 8]      = __float2half_rn(c[mt][nt][2] * INV32);
                g_Vt[vb + SS + 8] = __float2half_rn(c[mt][nt][3] * INV32);
            }
        }
    } else {
#pragma unroll
        for (int mt = 0; mt < 4; mt++) {
            size_t row0 = (size_t)rowBase + wm * 64 + mt * 16 + g;
#pragma unroll
            for (int nt = 0; nt < 8; nt++) {
                int col = colBase + wn * 64 + nt * 8 + 2 * tig;
                float2 x0 = *(const float2*)(AuxX + row0 * EE + col);
                float2 x1 = *(const float2*)(AuxX + (row0 + 8) * EE + col);
                *(float2*)(g_R + row0 * EE + col) =
                    make_float2(c[mt][nt][0] * INV32 + x0.x, c[mt][nt][1] * INV32 + x0.y);
                *(float2*)(g_R + (row0 + 8) * EE + col) =
                    make_float2(c[mt][nt][2] * INV32 + x1.x, c[mt][nt][3] * INV32 + x1.y);
            }
        }
    }
}

// ---------------- flash attention: fp16, PV single-term, 3 CTAs/SM ----------
// (reverted to R9 structure — pipelined variant regressed)
#define AROW 144
#define ATILE (64 * AROW)                  /* 9216 */
#define ABUF (3 * ATILE)                   /* Kh, Kl, V = 27648 */
#define ATTN_SMEM (2 * ABUF)               /* 55296 */

__global__ __launch_bounds__(128, 3) void attn_kernel()
{
    extern __shared__ char smb[];
    const uint32_t sbase = smem_u32(smb);

    const int qt = blockIdx.x;     // 0..15 (64 q rows each)
    const int h  = blockIdx.y;
    const int b  = blockIdx.z;
    const int tid = threadIdx.x;
    const int wid = tid >> 5;      // 0..3
    const int lane = tid & 31;
    const int g = lane >> 2;
    const int tig = lane & 3;

    const size_t kbase0 = ((size_t)b * SS) * EE + h * 64;
    const size_t vbase0 = ((size_t)(b * HH + h) * 64) * SS;

    auto issue = [&](int kt, int stage) {
        uint32_t sb = sbase + stage * ABUF;
#pragma unroll
        for (int i = 0; i < 4; i++) {
            int ch = tid + i * 128;        // 0..511
            int r = ch >> 3;               // 0..63
            int cb = (ch & 7) * 16;
            int c8 = (ch & 7) * 8;
            size_t ko = kbase0 + (size_t)(kt * 64 + r) * EE + c8;
            size_t vo = vbase0 + (size_t)r * SS + kt * 64 + c8;
            uint32_t off = r * AROW + cb;
            cp16(sb + off,             g_Kh + ko);
            cp16(sb + ATILE + off,     g_Kl + ko);
            cp16(sb + 2 * ATILE + off, g_Vt + vo);
        }
        CP_COMMIT;
    };

    issue(0, 0);

    // ---- Q fragments (held all kernel; log2e pre-folded) ----
    uint32_t qh[4][4], ql[4][4];
    {
        size_t rg = (size_t)(b * SS + qt * 64 + wid * 16 + g);
        const __half* ph = g_Qh + rg * EE + h * 64;
        const __half* pl = g_Ql + rg * EE + h * 64;
#pragma unroll
        for (int ks = 0; ks < 4; ks++) {
            int c0 = ks * 16 + 2 * tig;
            qh[ks][0] = *(const uint32_t*)(ph + c0);
            qh[ks][1] = *(const uint32_t*)(ph + 8 * EE + c0);
            qh[ks][2] = *(const uint32_t*)(ph + c0 + 8);
            qh[ks][3] = *(const uint32_t*)(ph + 8 * EE + c0 + 8);
            ql[ks][0] = *(const uint32_t*)(pl + c0);
            ql[ks][1] = *(const uint32_t*)(pl + 8 * EE + c0);
            ql[ks][2] = *(const uint32_t*)(pl + c0 + 8);
            ql[ks][3] = *(const uint32_t*)(pl + 8 * EE + c0 + 8);
        }
    }

    float acc[8][4];
#pragma unroll
    for (int j = 0; j < 8; j++)
#pragma unroll
        for (int r = 0; r < 4; r++) acc[j][r] = 0.f;
    float m0 = -1e30f, m1 = -1e30f, l0 = 0.f, l1 = 0.f;

    const uint32_t fLane = (uint32_t)((lane & 7) + ((lane >> 4) & 1) * 8) * AROW
                         + ((lane >> 3) & 1) * 16;

    for (int kt = 0; kt < 16; kt++) {
        CP_WAIT(0);
        __syncthreads();
        if (kt < 15) issue(kt + 1, (kt + 1) & 1);

        const uint32_t sb = sbase + (kt & 1) * ABUF;
        const uint32_t kOff = sb + fLane;
        const uint32_t vOff = sb + 2 * ATILE + fLane;

        // ---- scores (log2 domain), fp16 3-term ----
        float c[8][4];
#pragma unroll
        for (int j = 0; j < 8; j++)
#pragma unroll
            for (int r = 0; r < 4; r++) c[j][r] = 0.f;

#pragma unroll
        for (int ks = 0; ks < 4; ks++) {
            uint32_t bh[4][4], bl[4][4];
#pragma unroll
            for (int p = 0; p < 4; p++) {
                ldsm4(bh[p], kOff + p * 16 * AROW + ks * 32);
                ldsm4(bl[p], kOff + ATILE + p * 16 * AROW + ks * 32);
            }
#pragma unroll
            for (int p = 0; p < 4; p++) {
                mma_f16(c[2 * p],     qh[ks], bh[p][0], bh[p][1]);
                mma_f16(c[2 * p + 1], qh[ks], bh[p][2], bh[p][3]);
            }
#pragma unroll
            for (int p = 0; p < 4; p++) {
                mma_f16(c[2 * p],     qh[ks], bl[p][0], bl[p][1]);
                mma_f16(c[2 * p + 1], qh[ks], bl[p][2], bl[p][3]);
            }
#pragma unroll
            for (int p = 0; p < 4; p++) {
                mma_f16(c[2 * p],     ql[ks], bh[p][0], bh[p][1]);
                mma_f16(c[2 * p + 1], ql[ks], bh[p][2], bh[p][3]);
            }
        }

        // ---- online softmax (exp2 domain) ----
        float mx0 = -1e30f, mx1 = -1e30f;
#pragma unroll
        for (int j = 0; j < 8; j++) {
            mx0 = fmaxf(mx0, fmaxf(c[j][0], c[j][1]));
            mx1 = fmaxf(mx1, fmaxf(c[j][2], c[j][3]));
        }
        mx0 = fmaxf(mx0, __shfl_xor_sync(0xffffffffu, mx0, 1));
        mx0 = fmaxf(mx0, __shfl_xor_sync(0xffffffffu, mx0, 2));
        mx1 = fmaxf(mx1, __shfl_xor_sync(0xffffffffu, mx1, 1));
        mx1 = fmaxf(mx1, __shfl_xor_sync(0xffffffffu, mx1, 2));
        float mn0 = fmaxf(m0, mx0), mn1 = fmaxf(m1, mx1);
        float cr0 = exp2f(m0 - mn0), cr1 = exp2f(m1 - mn1);
        float s0 = 0.f, s1 = 0.f;
#pragma unroll
        for (int j = 0; j < 8; j++) {
            c[j][0] = exp2f(c[j][0] - mn0);
            c[j][1] = exp2f(c[j][1] - mn0);
            c[j][2] = exp2f(c[j][2] - mn1);
            c[j][3] = exp2f(c[j][3] - mn1);
            s0 += c[j][0] + c[j][1];
            s1 += c[j][2] + c[j][3];
        }
        s0 += __shfl_xor_sync(0xffffffffu, s0, 1);
        s0 += __shfl_xor_sync(0xffffffffu, s0, 2);
        s1 += __shfl_xor_sync(0xffffffffu, s1, 1);
        s1 += __shfl_xor_sync(0xffffffffu, s1, 2);
        l0 = l0 * cr0 + s0;
        l1 = l1 * cr1 + s1;
        m0 = mn0; m1 = mn1;
#pragma unroll
        for (int j = 0; j < 8; j++) {
            acc[j][0] *= cr0; acc[j][1] *= cr0;
            acc[j][2] *= cr1; acc[j][3] *= cr1;
        }

        // ---- PV: single term, P and V fp16 ----
#pragma unroll
        for (int ks = 0; ks < 4; ks++) {
            uint32_t ph[4];
            ph[0] = packh2(c[2 * ks][0],     c[2 * ks][1]);
            ph[1] = packh2(c[2 * ks][2],     c[2 * ks][3]);
            ph[2] = packh2(c[2 * ks + 1][0], c[2 * ks + 1][1]);
            ph[3] = packh2(c[2 * ks + 1][2], c[2 * ks + 1][3]);
            uint32_t vh[4][4];
#pragma unroll
            for (int p = 0; p < 4; p++)
                ldsm4(vh[p], vOff + p * 16 * AROW + ks * 32);
#pragma unroll
            for (int p = 0; p < 4; p++) {
                mma_f16(acc[2 * p],     ph, vh[p][0], vh[p][1]);
                mma_f16(acc[2 * p + 1], ph, vh[p][2], vh[p][3]);
            }
        }
    }

    // ---- epilogue: O = acc/l, write fp16 hi/lo ----
    float i0 = 1.f / l0, i1 = 1.f / l1;
    size_t rg = (size_t)(b * SS + qt * 64 + wid * 16 + g);
#pragma unroll
    for (int j = 0; j < 8; j++) {
        int col = h * 64 + j * 8 + 2 * tig;
        uint32_t hh, ll;
        split2(acc[j][0] * i0, acc[j][1] * i0, hh, ll);
        *(uint32_t*)(g_Oh + rg * EE + col) = hh;
        *(uint32_t*)(g_Ol + rg * EE + col) = ll;
        split2(acc[j][2] * i1, acc[j][3] * i1, hh, ll);
        *(uint32_t*)(g_Oh + (rg + 8) * EE + col) = hh;
        *(uint32_t*)(g_Ol + (rg + 8) * EE + col) = ll;
    }
}

// ---------------- LayerNorm ----------------
__global__ __launch_bounds__(256) void ln_kernel(
    const float* __restrict__ gamma, const float* __restrict__ beta,
    float* __restrict__ out)
{
    const int row = blockIdx.x;
    const int tid = threadIdx.x;
    const float4 v = *(const float4*)(g_R + (size_t)row * EE + tid * 4);

    float s1 = v.x + v.y + v.z + v.w;
    float s2 = v.x * v.x + v.y * v.y + v.z * v.z + v.w * v.w;

    __shared__ float sh1[8], sh2[8];
#pragma unroll
    for (int off = 16; off > 0; off >>= 1) {
        s1 += __shfl_xor_sync(0xffffffffu, s1, off);
        s2 += __shfl_xor_sync(0xffffffffu, s2, off);
    }
    const int warp = tid >> 5;
    if ((tid & 31) == 0) { sh1[warp] = s1; sh2[warp] = s2; }
    __syncthreads();
    float t1 = 0.f, t2 = 0.f;
#pragma unroll
    for (int w = 0; w < 8; w++) { t1 += sh1[w]; t2 += sh2[w]; }

    const float mean = t1 * (1.0f / EE);
    const float var  = t2 * (1.0f / EE) - mean * mean;
    const float inv  = rsqrtf(var + 1e-6f);

    const float4 gmv = *(const float4*)(gamma + tid * 4);
    const float4 btv = *(const float4*)(beta + tid * 4);
    float4 o;
    o.x = (v.x - mean) * inv * gmv.x + btv.x;
    o.y = (v.y - mean) * inv * gmv.y + btv.y;
    o.z = (v.z - mean) * inv * gmv.z + btv.z;
    o.w = (v.w - mean) * inv * gmv.w + btv.w;
    *(float4*)(out + (size_t)row * EE + tid * 4) = o;
}

// ---------------------------------------------------------------------------
extern "C" void kernel_launch(void* const* d_in, const int* in_sizes, int n_in,
                              void* d_out, int out_size)
{
    const float* X     = (const float*)d_in[0];
    const float* gQ    = (const float*)d_in[1];
    const float* gK    = (const float*)d_in[2];
    const float* Wq    = (const float*)d_in[3];
    const float* Wk    = (const float*)d_in[4];
    const float* Wv    = (const float*)d_in[5];
    const float* Wo    = (const float*)d_in[6];
    const float* gamma = (const float*)d_in[7];
    const float* beta  = (const float*)d_in[8];
    float* out = (float*)d_out;

    cudaFuncSetAttribute(gemm_kernel,
                         cudaFuncAttributeMaxDynamicSharedMemorySize, GEMM_SMEM);
    cudaFuncSetAttribute(attn_kernel,
                         cudaFuncAttributeMaxDynamicSharedMemorySize, ATTN_SMEM);

    prep_x_kernel<<<NELEM / 1024, 256>>>(X);
    prep_w_kernel<<<dim3(32, 32, 4), dim3(32, 8)>>>(Wq, Wk, Wv, Wo);

    gemm_kernel<<<dim3(8, 64, 3), 128, GEMM_SMEM>>>(gQ, gK, X, 0);

    attn_kernel<<<dim3(16, HH, BB), 128, ATTN_SMEM>>>();

    gemm_kernel<<<dim3(8, 64, 1), 128, GEMM_SMEM>>>(gQ, gK, X, 3);
    ln_kernel<<<M_TOT, 256>>>(gamma, beta, out);
}

// round 12
// speedup vs baseline: 1.1888x; 1.0240x over previous
#include <cuda_runtime.h>
#include <cuda_fp16.h>
#include <stdint.h>

#define BB 8
#define SS 1024
#define EE 1024
#define HH 16
#define M_TOT 8192
#define NELEM ((size_t)M_TOT * EE)   /* 8388608 */

// ---------------- scratch (device globals; no allocations) ----------------
__device__ __half g_Xh[NELEM], g_Xl[NELEM];
__device__ __half g_Wth[4 * 1048576], g_Wtl[4 * 1048576];  // [N][K], scaled x32
__device__ __half g_Qh[NELEM], g_Ql[NELEM];   // gate*2*0.125*log2e folded
__device__ __half g_Kh[NELEM], g_Kl[NELEM];   // gate*2 folded
__device__ __half g_Vt[NELEM];                // [(b*H+h)*64+d][s], single fp16
__device__ __half g_Oh[NELEM], g_Ol[NELEM];
__device__ float g_R[NELEM];

// ---------------- helpers ----------------
__device__ __forceinline__ void mma_f16(float* c, const uint32_t* a,
                                        uint32_t b0, uint32_t b1) {
    asm volatile(
        "mma.sync.aligned.m16n8k16.row.col.f32.f16.f16.f32 "
        "{%0,%1,%2,%3}, {%4,%5,%6,%7}, {%8,%9}, {%0,%1,%2,%3};"
        : "+f"(c[0]), "+f"(c[1]), "+f"(c[2]), "+f"(c[3])
        : "r"(a[0]), "r"(a[1]), "r"(a[2]), "r"(a[3]), "r"(b0), "r"(b1));
}

__device__ __forceinline__ void ldsm4(uint32_t* r, uint32_t addr) {
    asm volatile("ldmatrix.sync.aligned.m8n8.x4.shared.b16 {%0,%1,%2,%3}, [%4];"
                 : "=r"(r[0]), "=r"(r[1]), "=r"(r[2]), "=r"(r[3]) : "r"(addr));
}

__device__ __forceinline__ void cp16(uint32_t s, const void* g) {
    asm volatile("cp.async.cg.shared.global [%0], [%1], 16;" :: "r"(s), "l"(g));
}
#define CP_COMMIT asm volatile("cp.async.commit_group;" ::: "memory")
#define CP_WAIT(n) asm volatile("cp.async.wait_group %0;" :: "n"(n) : "memory")

__device__ __forceinline__ uint32_t smem_u32(const void* p) {
    uint32_t a;
    asm("{ .reg .u64 t; cvta.to.shared.u64 t, %1; cvt.u32.u64 %0, t; }"
        : "=r"(a) : "l"(p));
    return a;
}

__device__ __forceinline__ void split2(float x, float y, uint32_t& h, uint32_t& l) {
    __half2 hh = __floats2half2_rn(x, y);
    __half2 ll = __floats2half2_rn(x - __low2float(hh), y - __high2float(hh));
    h = *(uint32_t*)&hh;
    l = *(uint32_t*)&ll;
}

__device__ __forceinline__ uint32_t packh2(float x, float y) {
    __half2 hh = __floats2half2_rn(x, y);
    return *(uint32_t*)&hh;
}

__device__ __forceinline__ void split1(float x, __half& h, __half& l) {
    h = __float2half_rn(x);
    l = __float2half_rn(x - __half2float(h));
}

// ---------------- prep: split X into fp16 hi/lo ----------------
__global__ __launch_bounds__(256) void prep_x_kernel(const float* __restrict__ X)
{
    size_t i = ((size_t)blockIdx.x * 256 + threadIdx.x) * 4;
    float4 v = *(const float4*)(X + i);
    uint32_t h01, l01, h23, l23;
    split2(v.x, v.y, h01, l01);
    split2(v.z, v.w, h23, l23);
    *(uint32_t*)(g_Xh + i)     = h01;
    *(uint32_t*)(g_Xh + i + 2) = h23;
    *(uint32_t*)(g_Xl + i)     = l01;
    *(uint32_t*)(g_Xl + i + 2) = l23;
}

// ---------------- prep: weights x32 -> K-major fp16 hi/lo ----------------
__global__ __launch_bounds__(256) void prep_w_kernel(
    const float* __restrict__ Wq, const float* __restrict__ Wk,
    const float* __restrict__ Wv, const float* __restrict__ Wo)
{
    const int which = blockIdx.z;
    const float* W = (which == 0) ? Wq : (which == 1) ? Wk : (which == 2) ? Wv : Wo;
    __half* Oh = g_Wth + (size_t)which * 1048576;
    __half* Ol = g_Wtl + (size_t)which * 1048576;

    __shared__ float tile[32][33];
    const int tx = threadIdx.x, ty = threadIdx.y;
    const int n0 = blockIdx.x * 32, k0 = blockIdx.y * 32;

    if (which < 3) {
#pragma unroll
        for (int i = 0; i < 4; i++)
            tile[ty + 8 * i][tx] = W[(size_t)(k0 + ty + 8 * i) * EE + n0 + tx];
        __syncthreads();
#pragma unroll
        for (int i = 0; i < 4; i++) {
            float v = tile[tx][ty + 8 * i] * 32.0f;
            __half h, l;
            split1(v, h, l);
            size_t o = (size_t)(n0 + ty + 8 * i) * EE + k0 + tx;
            Oh[o] = h; Ol[o] = l;
        }
    } else {
#pragma unroll
        for (int i = 0; i < 4; i++) {
            size_t o = (size_t)(n0 + ty + 8 * i) * EE + k0 + tx;
            float v = W[o] * 32.0f;
            __half h, l;
            split1(v, h, l);
            Oh[o] = h; Ol[o] = l;
        }
    }
}

// ---------------- GEMM: 64x64 warp tiles, CTA 128x128, 2 CTAs/SM ------------
// modes 0,1 (Q,K): 3-term. modes 2,3 (V,out-proj): 1-term (Ah*Bh only).
#define GROW 80                            /* 64B data + 16 pad */
#define GTILE (128 * GROW)                 /* 10240 */
#define GSTAGE (4 * GTILE)                 /* Ah, Al, Bh, Bl = 40960 */
#define GEMM_SMEM (2 * GSTAGE)             /* 81920 */
#define INV32 0.03125f

__global__ __launch_bounds__(128, 2) void gemm_kernel(
    const float* __restrict__ AuxQ, const float* __restrict__ AuxK,
    const float* __restrict__ AuxX, int modeBase)
{
    extern __shared__ char smb[];
    const uint32_t sbase = smem_u32(smb);

    const int mode = modeBase + blockIdx.z;
    const bool threeTerm = (mode <= 1);
    const __half* Ahp = (mode == 3) ? g_Oh : g_Xh;
    const __half* Alp = (mode == 3) ? g_Ol : g_Xl;
    const __half* Bhp = g_Wth + (size_t)mode * 1048576;
    const __half* Blp = g_Wtl + (size_t)mode * 1048576;

    const int tid = threadIdx.x;
    const int wid = tid >> 5;
    const int lane = tid & 31;
    const int g = lane >> 2;
    const int tig = lane & 3;
    const int wm = wid >> 1;
    const int wn = wid & 1;
    const int colBase = blockIdx.x * 128;
    const int rowBase = blockIdx.y * 128;

    float c[4][8][4];
#pragma unroll
    for (int mt = 0; mt < 4; mt++)
#pragma unroll
        for (int nt = 0; nt < 8; nt++)
#pragma unroll
            for (int r = 0; r < 4; r++) c[mt][nt][r] = 0.f;

    const uint32_t aLane = (uint32_t)(wm * 64 + (lane & 7) + ((lane >> 3) & 1) * 8) * GROW
                         + ((lane >> 4) & 1) * 16;
    const uint32_t bLane = (uint32_t)(wn * 64 + (lane & 7) + ((lane >> 4) & 1) * 8) * GROW
                         + ((lane >> 3) & 1) * 16;

    auto issue = [&](int kt, int stage) {
        uint32_t sb = sbase + stage * GSTAGE;
#pragma unroll
        for (int i = 0; i < 4; i++) {
            int ch = tid + i * 128;
            int r = ch >> 2;
            int cb = (ch & 3) * 16;
            int c8 = (ch & 3) * 8;
            size_t ao = (size_t)(rowBase + r) * EE + kt * 32 + c8;
            uint32_t off = r * GROW + cb;
            cp16(sb + off, Ahp + ao);
            if (threeTerm)
                cp16(sb + GTILE + off, Alp + ao);
        }
#pragma unroll
        for (int i = 0; i < 4; i++) {
            int ch = tid + i * 128;
            int r = ch >> 2;
            int cb = (ch & 3) * 16;
            int c8 = (ch & 3) * 8;
            size_t bo = (size_t)(colBase + r) * EE + kt * 32 + c8;
            uint32_t off = r * GROW + cb;
            cp16(sb + 2 * GTILE + off, Bhp + bo);
            if (threeTerm)
                cp16(sb + 3 * GTILE + off, Blp + bo);
        }
        CP_COMMIT;
    };

    issue(0, 0);

    for (int kt = 0; kt < 32; kt++) {
        CP_WAIT(0);
        __syncthreads();
        if (kt + 1 < 32) issue(kt + 1, (kt + 1) & 1);

        const uint32_t sb = sbase + (kt & 1) * GSTAGE;
        const uint32_t aOff = sb + aLane;
        const uint32_t bOff = sb + 2 * GTILE + bLane;

#pragma unroll
        for (int ks = 0; ks < 2; ks++) {
            uint32_t ah[4][4], bh[4][4];
#pragma unroll
            for (int mt = 0; mt < 4; mt++)
                ldsm4(ah[mt], aOff + mt * 16 * GROW + ks * 32);
#pragma unroll
            for (int p = 0; p < 4; p++)
                ldsm4(bh[p], bOff + p * 16 * GROW + ks * 32);
            // pass 1: Ah*Bh — always
#pragma unroll
            for (int p = 0; p < 4; p++)
#pragma unroll
                for (int mt = 0; mt < 4; mt++) {
                    mma_f16(c[mt][2 * p],     ah[mt], bh[p][0], bh[p][1]);
                    mma_f16(c[mt][2 * p + 1], ah[mt], bh[p][2], bh[p][3]);
                }
            if (threeTerm) {
                // pass 2: Al*Bh
                uint32_t al[4][4];
#pragma unroll
                for (int mt = 0; mt < 4; mt++)
                    ldsm4(al[mt], aOff + GTILE + mt * 16 * GROW + ks * 32);
#pragma unroll
                for (int p = 0; p < 4; p++)
#pragma unroll
                    for (int mt = 0; mt < 4; mt++) {
                        mma_f16(c[mt][2 * p],     al[mt], bh[p][0], bh[p][1]);
                        mma_f16(c[mt][2 * p + 1], al[mt], bh[p][2], bh[p][3]);
                    }
                // pass 3: Ah*Bl
                uint32_t bl[4][4];
#pragma unroll
                for (int p = 0; p < 4; p++)
                    ldsm4(bl[p], bOff + GTILE + p * 16 * GROW + ks * 32);
#pragma unroll
                for (int p = 0; p < 4; p++)
#pragma unroll
                    for (int mt = 0; mt < 4; mt++) {
                        mma_f16(c[mt][2 * p],     ah[mt], bl[p][0], bl[p][1]);
                        mma_f16(c[mt][2 * p + 1], ah[mt], bl[p][2], bl[p][3]);
                    }
            }
        }
    }

    // ---- epilogues (fold 1/32 from weight scaling) ----
    const int batch = rowBase / SS;
    if (mode <= 1) {
        __half* Oh = (mode == 0) ? g_Qh : g_Kh;
        __half* Ol = (mode == 0) ? g_Ql : g_Kl;
        const float sc = ((mode == 0) ? 0.25f * 1.44269504089f : 2.0f) * INV32;
        const float* Aux = (mode == 0) ? AuxQ : AuxK;
#pragma unroll
        for (int mt = 0; mt < 4; mt++) {
            size_t row0 = (size_t)rowBase + wm * 64 + mt * 16 + g;
#pragma unroll
            for (int nt = 0; nt < 8; nt++) {
                int col = colBase + wn * 64 + nt * 8 + 2 * tig;
                float2 gv = *(const float2*)(Aux + (size_t)batch * EE + col);
                float gx = gv.x * sc, gy = gv.y * sc;
                uint32_t h, l;
                split2(c[mt][nt][0] * gx, c[mt][nt][1] * gy, h, l);
                *(uint32_t*)(Oh + row0 * EE + col) = h;
                *(uint32_t*)(Ol + row0 * EE + col) = l;
                split2(c[mt][nt][2] * gx, c[mt][nt][3] * gy, h, l);
                *(uint32_t*)(Oh + (row0 + 8) * EE + col) = h;
                *(uint32_t*)(Ol + (row0 + 8) * EE + col) = l;
            }
        }
    } else if (mode == 2) {
#pragma unroll
        for (int mt = 0; mt < 4; mt++) {
            int row0 = rowBase + wm * 64 + mt * 16 + g;
            int s = row0 - batch * SS;
#pragma unroll
            for (int nt = 0; nt < 8; nt++) {
                int col = colBase + wn * 64 + nt * 8 + 2 * tig;
                int hh = col >> 6, d = col & 63;
                size_t vb = ((size_t)(batch * HH + hh) * 64 + d) * SS + s;
                g_Vt[vb]          = __float2half_rn(c[mt][nt][0] * INV32);
                g_Vt[vb + SS]     = __float2half_rn(c[mt][nt][1] * INV32);
                g_Vt[vb + 8]      = __float2half_rn(c[mt][nt][2] * INV32);
                g_Vt[vb + SS + 8] = __float2half_rn(c[mt][nt][3] * INV32);
            }
        }
    } else {
#pragma unroll
        for (int mt = 0; mt < 4; mt++) {
            size_t row0 = (size_t)rowBase + wm * 64 + mt * 16 + g;
#pragma unroll
            for (int nt = 0; nt < 8; nt++) {
                int col = colBase + wn * 64 + nt * 8 + 2 * tig;
                float2 x0 = *(const float2*)(AuxX + row0 * EE + col);
                float2 x1 = *(const float2*)(AuxX + (row0 + 8) * EE + col);
                *(float2*)(g_R + row0 * EE + col) =
                    make_float2(c[mt][nt][0] * INV32 + x0.x, c[mt][nt][1] * INV32 + x0.y);
                *(float2*)(g_R + (row0 + 8) * EE + col) =
                    make_float2(c[mt][nt][2] * INV32 + x1.x, c[mt][nt][3] * INV32 + x1.y);
            }
        }
    }
}

// ---- flash attention: q-tile 128 (Q resident in smem), halved K/V traffic ----
#define AROW 144
#define ATILE (64 * AROW)                  /* 9216: one K or V tile */
#define QTILE (128 * AROW)                 /* 18432: Qh or Ql resident */
#define ABUF (3 * ATILE)                   /* Kh, Kl, V = 27648 per stage */
#define SM_RING (2 * QTILE)                /* ring base = 36864 */
#define ATTN_SMEM (2 * QTILE + 2 * ABUF)   /* 92160 */

__global__ __launch_bounds__(128, 2) void attn_kernel()
{
    extern __shared__ char smb[];
    const uint32_t sbase = smem_u32(smb);

    const int qt = blockIdx.x;     // 0..7 (128 q rows each)
    const int h  = blockIdx.y;
    const int b  = blockIdx.z;
    const int tid = threadIdx.x;
    const int wid = tid >> 5;      // 0..3 (32 q rows each)
    const int lane = tid & 31;
    const int g = lane >> 2;
    const int tig = lane & 3;

    const size_t kbase0 = ((size_t)b * SS) * EE + h * 64;
    const size_t vbase0 = ((size_t)(b * HH + h) * 64) * SS;
    const size_t qrow0  = (size_t)(b * SS + qt * 128);

    auto issue = [&](int kt, int stage) {
        uint32_t sb = sbase + SM_RING + stage * ABUF;
#pragma unroll
        for (int i = 0; i < 4; i++) {
            int ch = tid + i * 128;        // 0..511
            int r = ch >> 3;               // 0..63
            int cb = (ch & 7) * 16;
            int c8 = (ch & 7) * 8;
            size_t ko = kbase0 + (size_t)(kt * 64 + r) * EE + c8;
            size_t vo = vbase0 + (size_t)r * SS + kt * 64 + c8;
            uint32_t off = r * AROW + cb;
            cp16(sb + off,             g_Kh + ko);
            cp16(sb + ATILE + off,     g_Kl + ko);
            cp16(sb + 2 * ATILE + off, g_Vt + vo);
        }
        CP_COMMIT;
    };

    // ---- load Q (hi+lo) into resident smem ----
#pragma unroll
    for (int i = 0; i < 8; i++) {
        int ch = tid + i * 128;            // 0..1023
        int r = ch >> 3;                   // 0..127
        int cb = (ch & 7) * 16;
        int c8 = (ch & 7) * 8;
        uint32_t off = r * AROW + cb;
        size_t go = (qrow0 + r) * EE + h * 64 + c8;
        cp16(sbase + off,         g_Qh + go);
        cp16(sbase + QTILE + off, g_Ql + go);
    }
    CP_COMMIT;
    issue(0, 0);

    float acc[2][8][4];
#pragma unroll
    for (int mt = 0; mt < 2; mt++)
#pragma unroll
        for (int j = 0; j < 8; j++)
#pragma unroll
            for (int r = 0; r < 4; r++) acc[mt][j][r] = 0.f;
    float mm[2][2] = {{-1e30f, -1e30f}, {-1e30f, -1e30f}};
    float ll[2][2] = {{0.f, 0.f}, {0.f, 0.f}};

    // B-operand lane addr (K, V); A-operand lane addr (Q)
    const uint32_t fLane = (uint32_t)((lane & 7) + ((lane >> 4) & 1) * 8) * AROW
                         + ((lane >> 3) & 1) * 16;
    const uint32_t qLane = (uint32_t)((lane & 7) + ((lane >> 3) & 1) * 8) * AROW
                         + ((lane >> 4) & 1) * 16;

    for (int kt = 0; kt < 16; kt++) {
        CP_WAIT(0);
        __syncthreads();
        if (kt < 15) issue(kt + 1, (kt + 1) & 1);

        const uint32_t kOff = sbase + SM_RING + (kt & 1) * ABUF + fLane;
        const uint32_t vOff = kOff + 2 * ATILE;

#pragma unroll
        for (int mt = 0; mt < 2; mt++) {
            const uint32_t qOff = sbase + (uint32_t)(wid * 32 + mt * 16) * AROW + qLane;

            // ---- scores (log2 domain), fp16 3-term ----
            float c[8][4];
#pragma unroll
            for (int j = 0; j < 8; j++)
#pragma unroll
                for (int r = 0; r < 4; r++) c[j][r] = 0.f;

#pragma unroll
            for (int ks = 0; ks < 4; ks++) {
                uint32_t qh[4], ql[4];
                ldsm4(qh, qOff + ks * 32);
                ldsm4(ql, qOff + QTILE + ks * 32);
                uint32_t bh[4][4], bl[4][4];
#pragma unroll
                for (int p = 0; p < 4; p++) {
                    ldsm4(bh[p], kOff + p * 16 * AROW + ks * 32);
                    ldsm4(bl[p], kOff + ATILE + p * 16 * AROW + ks * 32);
                }
#pragma unroll
                for (int p = 0; p < 4; p++) {
                    mma_f16(c[2 * p],     qh, bh[p][0], bh[p][1]);
                    mma_f16(c[2 * p + 1], qh, bh[p][2], bh[p][3]);
                }
#pragma unroll
                for (int p = 0; p < 4; p++) {
                    mma_f16(c[2 * p],     qh, bl[p][0], bl[p][1]);
                    mma_f16(c[2 * p + 1], qh, bl[p][2], bl[p][3]);
                }
#pragma unroll
                for (int p = 0; p < 4; p++) {
                    mma_f16(c[2 * p],     ql, bh[p][0], bh[p][1]);
                    mma_f16(c[2 * p + 1], ql, bh[p][2], bh[p][3]);
                }
            }

            // ---- online softmax (exp2 domain) ----
            float mx0 = -1e30f, mx1 = -1e30f;
#pragma unroll
            for (int j = 0; j < 8; j++) {
                mx0 = fmaxf(mx0, fmaxf(c[j][0], c[j][1]));
                mx1 = fmaxf(mx1, fmaxf(c[j][2], c[j][3]));
            }
            mx0 = fmaxf(mx0, __shfl_xor_sync(0xffffffffu, mx0, 1));
            mx0 = fmaxf(mx0, __shfl_xor_sync(0xffffffffu, mx0, 2));
            mx1 = fmaxf(mx1, __shfl_xor_sync(0xffffffffu, mx1, 1));
            mx1 = fmaxf(mx1, __shfl_xor_sync(0xffffffffu, mx1, 2));
            float mn0 = fmaxf(mm[mt][0], mx0), mn1 = fmaxf(mm[mt][1], mx1);
            float cr0 = exp2f(mm[mt][0] - mn0), cr1 = exp2f(mm[mt][1] - mn1);
            float s0 = 0.f, s1 = 0.f;
#pragma unroll
            for (int j = 0; j < 8; j++) {
                c[j][0] = exp2f(c[j][0] - mn0);
                c[j][1] = exp2f(c[j][1] - mn0);
                c[j][2] = exp2f(c[j][2] - mn1);
                c[j][3] = exp2f(c[j][3] - mn1);
                s0 += c[j][0] + c[j][1];
                s1 += c[j][2] + c[j][3];
            }
            s0 += __shfl_xor_sync(0xffffffffu, s0, 1);
            s0 += __shfl_xor_sync(0xffffffffu, s0, 2);
            s1 += __shfl_xor_sync(0xffffffffu, s1, 1);
            s1 += __shfl_xor_sync(0xffffffffu, s1, 2);
            ll[mt][0] = ll[mt][0] * cr0 + s0;
            ll[mt][1] = ll[mt][1] * cr1 + s1;
            mm[mt][0] = mn0; mm[mt][1] = mn1;
#pragma unroll
            for (int j = 0; j < 8; j++) {
                acc[mt][j][0] *= cr0; acc[mt][j][1] *= cr0;
                acc[mt][j][2] *= cr1; acc[mt][j][3] *= cr1;
            }

            // ---- PV: single term, P and V fp16 ----
#pragma unroll
            for (int ks = 0; ks < 4; ks++) {
                uint32_t ph[4];
                ph[0] = packh2(c[2 * ks][0],     c[2 * ks][1]);
                ph[1] = packh2(c[2 * ks][2],     c[2 * ks][3]);
                ph[2] = packh2(c[2 * ks + 1][0], c[2 * ks + 1][1]);
                ph[3] = packh2(c[2 * ks + 1][2], c[2 * ks + 1][3]);
                uint32_t vh[4][4];
#pragma unroll
                for (int p = 0; p < 4; p++)
                    ldsm4(vh[p], vOff + p * 16 * AROW + ks * 32);
#pragma unroll
                for (int p = 0; p < 4; p++) {
                    mma_f16(acc[mt][2 * p],     ph, vh[p][0], vh[p][1]);
                    mma_f16(acc[mt][2 * p + 1], ph, vh[p][2], vh[p][3]);
                }
            }
        }
    }

    // ---- epilogue: O = acc/l, write fp16 hi/lo ----
#pragma unroll
    for (int mt = 0; mt < 2; mt++) {
        float i0 = 1.f / ll[mt][0], i1 = 1.f / ll[mt][1];
        size_t rg = qrow0 + wid * 32 + mt * 16 + g;
#pragma unroll
        for (int j = 0; j < 8; j++) {
            int col = h * 64 + j * 8 + 2 * tig;
            uint32_t hh, lw;
            split2(acc[mt][j][0] * i0, acc[mt][j][1] * i0, hh, lw);
            *(uint32_t*)(g_Oh + rg * EE + col) = hh;
            *(uint32_t*)(g_Ol + rg * EE + col) = lw;
            split2(acc[mt][j][2] * i1, acc[mt][j][3] * i1, hh, lw);
            *(uint32_t*)(g_Oh + (rg + 8) * EE + col) = hh;
            *(uint32_t*)(g_Ol + (rg + 8) * EE + col) = lw;
        }
    }
}

// ---------------- LayerNorm ----------------
__global__ __launch_bounds__(256) void ln_kernel(
    const float* __restrict__ gamma, const float* __restrict__ beta,
    float* __restrict__ out)
{
    const int row = blockIdx.x;
    const int tid = threadIdx.x;
    const float4 v = *(const float4*)(g_R + (size_t)row * EE + tid * 4);

    float s1 = v.x + v.y + v.z + v.w;
    float s2 = v.x * v.x + v.y * v.y + v.z * v.z + v.w * v.w;

    __shared__ float sh1[8], sh2[8];
#pragma unroll
    for (int off = 16; off > 0; off >>= 1) {
        s1 += __shfl_xor_sync(0xffffffffu, s1, off);
        s2 += __shfl_xor_sync(0xffffffffu, s2, off);
    }
    const int warp = tid >> 5;
    if ((tid & 31) == 0) { sh1[warp] = s1; sh2[warp] = s2; }
    __syncthreads();
    float t1 = 0.f, t2 = 0.f;
#pragma unroll
    for (int w = 0; w < 8; w++) { t1 += sh1[w]; t2 += sh2[w]; }

    const float mean = t1 * (1.0f / EE);
    const float var  = t2 * (1.0f / EE) - mean * mean;
    const float inv  = rsqrtf(var + 1e-6f);

    const float4 gmv = *(const float4*)(gamma + tid * 4);
    const float4 btv = *(const float4*)(beta + tid * 4);
    float4 o;
    o.x = (v.x - mean) * inv * gmv.x + btv.x;
    o.y = (v.y - mean) * inv * gmv.y + btv.y;
    o.z = (v.z - mean) * inv * gmv.z + btv.z;
    o.w = (v.w - mean) * inv * gmv.w + btv.w;
    *(float4*)(out + (size_t)row * EE + tid * 4) = o;
}

// ---------------------------------------------------------------------------
extern "C" void kernel_launch(void* const* d_in, const int* in_sizes, int n_in,
                              void* d_out, int out_size)
{
    const float* X     = (const float*)d_in[0];
    const float* gQ    = (const float*)d_in[1];
    const float* gK    = (const float*)d_in[2];
    const float* Wq    = (const float*)d_in[3];
    const float* Wk    = (const float*)d_in[4];
    const float* Wv    = (const float*)d_in[5];
    const float* Wo    = (const float*)d_in[6];
    const float* gamma = (const float*)d_in[7];
    const float* beta  = (const float*)d_in[8];
    float* out = (float*)d_out;

    cudaFuncSetAttribute(gemm_kernel,
                         cudaFuncAttributeMaxDynamicSharedMemorySize, GEMM_SMEM);
    cudaFuncSetAttribute(attn_kernel,
                         cudaFuncAttributeMaxDynamicSharedMemorySize, ATTN_SMEM);

    prep_x_kernel<<<NELEM / 1024, 256>>>(X);
    prep_w_kernel<<<dim3(32, 32, 4), dim3(32, 8)>>>(Wq, Wk, Wv, Wo);

    gemm_kernel<<<dim3(8, 64, 3), 128, GEMM_SMEM>>>(gQ, gK, X, 0);

    attn_kernel<<<dim3(8, HH, BB), 128, ATTN_SMEM>>>();

    gemm_kernel<<<dim3(8, 64, 1), 128, GEMM_SMEM>>>(gQ, gK, X, 3);
    ln_kernel<<<M_TOT, 256>>>(gamma, beta, out);
}

// round 13
// speedup vs baseline: 1.2248x; 1.0303x over previous
#include <cuda_runtime.h>
#include <cuda_fp16.h>
#include <stdint.h>

#define BB 8
#define SS 1024
#define EE 1024
#define HH 16
#define M_TOT 8192
#define NELEM ((size_t)M_TOT * EE)   /* 8388608 */

// ---------------- scratch (device globals; no allocations) ----------------
__device__ __half g_Xh[NELEM], g_Xl[NELEM];
__device__ __half g_Wth[4 * 1048576], g_Wtl[4 * 1048576];  // [N][K], scaled x32
__device__ __half g_Qh[NELEM], g_Ql[NELEM];   // gate*2*0.125*log2e folded
__device__ __half g_Kh[NELEM], g_Kl[NELEM];   // gate*2 folded
__device__ __half g_Vt[NELEM];                // [(b*H+h)*64+d][s], single fp16
__device__ __half g_Oh[NELEM], g_Ol[NELEM];
__device__ float g_R[NELEM];

// ---------------- helpers ----------------
__device__ __forceinline__ void mma_f16(float* c, const uint32_t* a,
                                        uint32_t b0, uint32_t b1) {
    asm volatile(
        "mma.sync.aligned.m16n8k16.row.col.f32.f16.f16.f32 "
        "{%0,%1,%2,%3}, {%4,%5,%6,%7}, {%8,%9}, {%0,%1,%2,%3};"
        : "+f"(c[0]), "+f"(c[1]), "+f"(c[2]), "+f"(c[3])
        : "r"(a[0]), "r"(a[1]), "r"(a[2]), "r"(a[3]), "r"(b0), "r"(b1));
}

__device__ __forceinline__ void ldsm4(uint32_t* r, uint32_t addr) {
    asm volatile("ldmatrix.sync.aligned.m8n8.x4.shared.b16 {%0,%1,%2,%3}, [%4];"
                 : "=r"(r[0]), "=r"(r[1]), "=r"(r[2]), "=r"(r[3]) : "r"(addr));
}

__device__ __forceinline__ void cp16(uint32_t s, const void* g) {
    asm volatile("cp.async.cg.shared.global [%0], [%1], 16;" :: "r"(s), "l"(g));
}
#define CP_COMMIT asm volatile("cp.async.commit_group;" ::: "memory")
#define CP_WAIT(n) asm volatile("cp.async.wait_group %0;" :: "n"(n) : "memory")

__device__ __forceinline__ uint32_t smem_u32(const void* p) {
    uint32_t a;
    asm("{ .reg .u64 t; cvta.to.shared.u64 t, %1; cvt.u32.u64 %0, t; }"
        : "=r"(a) : "l"(p));
    return a;
}

__device__ __forceinline__ void split2(float x, float y, uint32_t& h, uint32_t& l) {
    __half2 hh = __floats2half2_rn(x, y);
    __half2 ll = __floats2half2_rn(x - __low2float(hh), y - __high2float(hh));
    h = *(uint32_t*)&hh;
    l = *(uint32_t*)&ll;
}

__device__ __forceinline__ uint32_t packh2(float x, float y) {
    __half2 hh = __floats2half2_rn(x, y);
    return *(uint32_t*)&hh;
}

__device__ __forceinline__ uint32_t ex2_h2(uint32_t x) {
    uint32_t r;
    asm("ex2.approx.f16x2 %0, %1;" : "=r"(r) : "r"(x));
    return r;
}

__device__ __forceinline__ void split1(float x, __half& h, __half& l) {
    h = __float2half_rn(x);
    l = __float2half_rn(x - __half2float(h));
}

// ---------------- prep: split X into fp16 hi/lo ----------------
__global__ __launch_bounds__(256) void prep_x_kernel(const float* __restrict__ X)
{
    size_t i = ((size_t)blockIdx.x * 256 + threadIdx.x) * 4;
    float4 v = *(const float4*)(X + i);
    uint32_t h01, l01, h23, l23;
    split2(v.x, v.y, h01, l01);
    split2(v.z, v.w, h23, l23);
    *(uint32_t*)(g_Xh + i)     = h01;
    *(uint32_t*)(g_Xh + i + 2) = h23;
    *(uint32_t*)(g_Xl + i)     = l01;
    *(uint32_t*)(g_Xl + i + 2) = l23;
}

// ---------------- prep: weights x32 -> K-major fp16 hi/lo ----------------
__global__ __launch_bounds__(256) void prep_w_kernel(
    const float* __restrict__ Wq, const float* __restrict__ Wk,
    const float* __restrict__ Wv, const float* __restrict__ Wo)
{
    const int which = blockIdx.z;
    const float* W = (which == 0) ? Wq : (which == 1) ? Wk : (which == 2) ? Wv : Wo;
    __half* Oh = g_Wth + (size_t)which * 1048576;
    __half* Ol = g_Wtl + (size_t)which * 1048576;

    __shared__ float tile[32][33];
    const int tx = threadIdx.x, ty = threadIdx.y;
    const int n0 = blockIdx.x * 32, k0 = blockIdx.y * 32;

    if (which < 3) {
#pragma unroll
        for (int i = 0; i < 4; i++)
            tile[ty + 8 * i][tx] = W[(size_t)(k0 + ty + 8 * i) * EE + n0 + tx];
        __syncthreads();
#pragma unroll
        for (int i = 0; i < 4; i++) {
            float v = tile[tx][ty + 8 * i] * 32.0f;
            __half h, l;
            split1(v, h, l);
            size_t o = (size_t)(n0 + ty + 8 * i) * EE + k0 + tx;
            Oh[o] = h; Ol[o] = l;
        }
    } else {
#pragma unroll
        for (int i = 0; i < 4; i++) {
            size_t o = (size_t)(n0 + ty + 8 * i) * EE + k0 + tx;
            float v = W[o] * 32.0f;
            __half h, l;
            split1(v, h, l);
            Oh[o] = h; Ol[o] = l;
        }
    }
}

// ---------------- GEMM: 64x64 warp tiles, CTA 128x128, 2 CTAs/SM ------------
// modes 0,1 (Q,K): 3-term. modes 2,3 (V,out-proj): 1-term (Ah*Bh only).
#define GROW 80                            /* 64B data + 16 pad */
#define GTILE (128 * GROW)                 /* 10240 */
#define GSTAGE (4 * GTILE)                 /* Ah, Al, Bh, Bl = 40960 */
#define GEMM_SMEM (2 * GSTAGE)             /* 81920 */
#define INV32 0.03125f
#define TSTR 136                           /* V transpose tile row stride (halves) */

__global__ __launch_bounds__(128, 2) void gemm_kernel(
    const float* __restrict__ AuxQ, const float* __restrict__ AuxK,
    const float* __restrict__ AuxX, int modeBase)
{
    extern __shared__ char smb[];
    const uint32_t sbase = smem_u32(smb);

    const int mode = modeBase + blockIdx.z;
    const bool threeTerm = (mode <= 1);
    const __half* Ahp = (mode == 3) ? g_Oh : g_Xh;
    const __half* Alp = (mode == 3) ? g_Ol : g_Xl;
    const __half* Bhp = g_Wth + (size_t)mode * 1048576;
    const __half* Blp = g_Wtl + (size_t)mode * 1048576;

    const int tid = threadIdx.x;
    const int wid = tid >> 5;
    const int lane = tid & 31;
    const int g = lane >> 2;
    const int tig = lane & 3;
    const int wm = wid >> 1;
    const int wn = wid & 1;
    const int colBase = blockIdx.x * 128;
    const int rowBase = blockIdx.y * 128;

    float c[4][8][4];
#pragma unroll
    for (int mt = 0; mt < 4; mt++)
#pragma unroll
        for (int nt = 0; nt < 8; nt++)
#pragma unroll
            for (int r = 0; r < 4; r++) c[mt][nt][r] = 0.f;

    const uint32_t aLane = (uint32_t)(wm * 64 + (lane & 7) + ((lane >> 3) & 1) * 8) * GROW
                         + ((lane >> 4) & 1) * 16;
    const uint32_t bLane = (uint32_t)(wn * 64 + (lane & 7) + ((lane >> 4) & 1) * 8) * GROW
                         + ((lane >> 3) & 1) * 16;

    auto issue = [&](int kt, int stage) {
        uint32_t sb = sbase + stage * GSTAGE;
#pragma unroll
        for (int i = 0; i < 4; i++) {
            int ch = tid + i * 128;
            int r = ch >> 2;
            int cb = (ch & 3) * 16;
            int c8 = (ch & 3) * 8;
            size_t ao = (size_t)(rowBase + r) * EE + kt * 32 + c8;
            uint32_t off = r * GROW + cb;
            cp16(sb + off, Ahp + ao);
            if (threeTerm)
                cp16(sb + GTILE + off, Alp + ao);
        }
#pragma unroll
        for (int i = 0; i < 4; i++) {
            int ch = tid + i * 128;
            int r = ch >> 2;
            int cb = (ch & 3) * 16;
            int c8 = (ch & 3) * 8;
            size_t bo = (size_t)(colBase + r) * EE + kt * 32 + c8;
            uint32_t off = r * GROW + cb;
            cp16(sb + 2 * GTILE + off, Bhp + bo);
            if (threeTerm)
                cp16(sb + 3 * GTILE + off, Blp + bo);
        }
        CP_COMMIT;
    };

    issue(0, 0);

    for (int kt = 0; kt < 32; kt++) {
        CP_WAIT(0);
        __syncthreads();
        if (kt + 1 < 32) issue(kt + 1, (kt + 1) & 1);

        const uint32_t sb = sbase + (kt & 1) * GSTAGE;
        const uint32_t aOff = sb + aLane;
        const uint32_t bOff = sb + 2 * GTILE + bLane;

#pragma unroll
        for (int ks = 0; ks < 2; ks++) {
            uint32_t ah[4][4], bh[4][4];
#pragma unroll
            for (int mt = 0; mt < 4; mt++)
                ldsm4(ah[mt], aOff + mt * 16 * GROW + ks * 32);
#pragma unroll
            for (int p = 0; p < 4; p++)
                ldsm4(bh[p], bOff + p * 16 * GROW + ks * 32);
            // pass 1: Ah*Bh — always
#pragma unroll
            for (int p = 0; p < 4; p++)
#pragma unroll
                for (int mt = 0; mt < 4; mt++) {
                    mma_f16(c[mt][2 * p],     ah[mt], bh[p][0], bh[p][1]);
                    mma_f16(c[mt][2 * p + 1], ah[mt], bh[p][2], bh[p][3]);
                }
            if (threeTerm) {
                // pass 2: Al*Bh
                uint32_t al[4][4];
#pragma unroll
                for (int mt = 0; mt < 4; mt++)
                    ldsm4(al[mt], aOff + GTILE + mt * 16 * GROW + ks * 32);
#pragma unroll
                for (int p = 0; p < 4; p++)
#pragma unroll
                    for (int mt = 0; mt < 4; mt++) {
                        mma_f16(c[mt][2 * p],     al[mt], bh[p][0], bh[p][1]);
                        mma_f16(c[mt][2 * p + 1], al[mt], bh[p][2], bh[p][3]);
                    }
                // pass 3: Ah*Bl
                uint32_t bl[4][4];
#pragma unroll
                for (int p = 0; p < 4; p++)
                    ldsm4(bl[p], bOff + GTILE + p * 16 * GROW + ks * 32);
#pragma unroll
                for (int p = 0; p < 4; p++)
#pragma unroll
                    for (int mt = 0; mt < 4; mt++) {
                        mma_f16(c[mt][2 * p],     ah[mt], bl[p][0], bl[p][1]);
                        mma_f16(c[mt][2 * p + 1], ah[mt], bl[p][2], bl[p][3]);
                    }
            }
        }
    }

    // ---- epilogues (fold 1/32 from weight scaling) ----
    const int batch = rowBase / SS;
    if (mode <= 1) {
        __half* Oh = (mode == 0) ? g_Qh : g_Kh;
        __half* Ol = (mode == 0) ? g_Ql : g_Kl;
        const float sc = ((mode == 0) ? 0.25f * 1.44269504089f : 2.0f) * INV32;
        const float* Aux = (mode == 0) ? AuxQ : AuxK;
#pragma unroll
        for (int mt = 0; mt < 4; mt++) {
            size_t row0 = (size_t)rowBase + wm * 64 + mt * 16 + g;
#pragma unroll
            for (int nt = 0; nt < 8; nt++) {
                int col = colBase + wn * 64 + nt * 8 + 2 * tig;
                float2 gv = *(const float2*)(Aux + (size_t)batch * EE + col);
                float gx = gv.x * sc, gy = gv.y * sc;
                uint32_t h, l;
                split2(c[mt][nt][0] * gx, c[mt][nt][1] * gy, h, l);
                *(uint32_t*)(Oh + row0 * EE + col) = h;
                *(uint32_t*)(Ol + row0 * EE + col) = l;
                split2(c[mt][nt][2] * gx, c[mt][nt][3] * gy, h, l);
                *(uint32_t*)(Oh + (row0 + 8) * EE + col) = h;
                *(uint32_t*)(Ol + (row0 + 8) * EE + col) = l;
            }
        }
    } else if (mode == 2) {
        // V: transpose through smem, then coalesced stores
        __syncthreads();
        __half* T = (__half*)smb;        // 128 (d) x TSTR
#pragma unroll
        for (int mt = 0; mt < 4; mt++) {
            int row = wm * 64 + mt * 16 + g;     // local s 0..127
#pragma unroll
            for (int nt = 0; nt < 8; nt++) {
                int cl = wn * 64 + nt * 8 + 2 * tig;  // local d 0..127
                T[(size_t)cl * TSTR + row]           = __float2half_rn(c[mt][nt][0] * INV32);
                T[(size_t)(cl + 1) * TSTR + row]     = __float2half_rn(c[mt][nt][1] * INV32);
                T[(size_t)cl * TSTR + row + 8]       = __float2half_rn(c[mt][nt][2] * INV32);
                T[(size_t)(cl + 1) * TSTR + row + 8] = __float2half_rn(c[mt][nt][3] * INV32);
            }
        }
        __syncthreads();
        const int s0 = rowBase & (SS - 1);
        const int dl = tid >> 2;
        const int ch = tid & 3;
#pragma unroll
        for (int pass = 0; pass < 4; pass++) {
            int d = dl + pass * 32;
            int gcol = colBase + d;
            int hh = gcol >> 6, dd = gcol & 63;
            size_t vb = ((size_t)(batch * HH + hh) * 64 + dd) * SS + s0 + ch * 32;
            uint4* dst = (uint4*)(g_Vt + vb);
            const uint4* src = (const uint4*)(T + (size_t)d * TSTR + ch * 32);
            dst[0] = src[0]; dst[1] = src[1]; dst[2] = src[2]; dst[3] = src[3];
        }
    } else {
#pragma unroll
        for (int mt = 0; mt < 4; mt++) {
            size_t row0 = (size_t)rowBase + wm * 64 + mt * 16 + g;
#pragma unroll
            for (int nt = 0; nt < 8; nt++) {
                int col = colBase + wn * 64 + nt * 8 + 2 * tig;
                float2 x0 = *(const float2*)(AuxX + row0 * EE + col);
                float2 x1 = *(const float2*)(AuxX + (row0 + 8) * EE + col);
                *(float2*)(g_R + row0 * EE + col) =
                    make_float2(c[mt][nt][0] * INV32 + x0.x, c[mt][nt][1] * INV32 + x0.y);
                *(float2*)(g_R + (row0 + 8) * EE + col) =
                    make_float2(c[mt][nt][2] * INV32 + x1.x, c[mt][nt][3] * INV32 + x1.y);
            }
        }
    }
}

// ---- flash attention: q-tile 128 (Q in smem), ex2.f16x2 softmax, MMA l-sum ----
#define AROW 144
#define ATILE (64 * AROW)                  /* 9216: one K or V tile */
#define QTILE (128 * AROW)                 /* 18432: Qh or Ql resident */
#define ABUF (3 * ATILE)                   /* Kh, Kl, V = 27648 per stage */
#define SM_RING (2 * QTILE)                /* ring base = 36864 */
#define ATTN_SMEM (2 * QTILE + 2 * ABUF)   /* 92160 */

__global__ __launch_bounds__(128, 2) void attn_kernel()
{
    extern __shared__ char smb[];
    const uint32_t sbase = smem_u32(smb);

    const int qt = blockIdx.x;     // 0..7 (128 q rows each)
    const int h  = blockIdx.y;
    const int b  = blockIdx.z;
    const int tid = threadIdx.x;
    const int wid = tid >> 5;      // 0..3 (32 q rows each)
    const int lane = tid & 31;
    const int g = lane >> 2;
    const int tig = lane & 3;

    const size_t kbase0 = ((size_t)b * SS) * EE + h * 64;
    const size_t vbase0 = ((size_t)(b * HH + h) * 64) * SS;
    const size_t qrow0  = (size_t)(b * SS + qt * 128);

    auto issue = [&](int kt, int stage) {
        uint32_t sb = sbase + SM_RING + stage * ABUF;
#pragma unroll
        for (int i = 0; i < 4; i++) {
            int ch = tid + i * 128;        // 0..511
            int r = ch >> 3;               // 0..63
            int cb = (ch & 7) * 16;
            int c8 = (ch & 7) * 8;
            size_t ko = kbase0 + (size_t)(kt * 64 + r) * EE + c8;
            size_t vo = vbase0 + (size_t)r * SS + kt * 64 + c8;
            uint32_t off = r * AROW + cb;
            cp16(sb + off,             g_Kh + ko);
            cp16(sb + ATILE + off,     g_Kl + ko);
            cp16(sb + 2 * ATILE + off, g_Vt + vo);
        }
        CP_COMMIT;
    };

    // ---- load Q (hi+lo) into resident smem ----
#pragma unroll
    for (int i = 0; i < 8; i++) {
        int ch = tid + i * 128;            // 0..1023
        int r = ch >> 3;                   // 0..127
        int cb = (ch & 7) * 16;
        int c8 = (ch & 7) * 8;
        uint32_t off = r * AROW + cb;
        size_t go = (qrow0 + r) * EE + h * 64 + c8;
        cp16(sbase + off,         g_Qh + go);
        cp16(sbase + QTILE + off, g_Ql + go);
    }
    CP_COMMIT;
    issue(0, 0);

    float acc[2][8][4];
#pragma unroll
    for (int mt = 0; mt < 2; mt++)
#pragma unroll
        for (int j = 0; j < 8; j++)
#pragma unroll
            for (int r = 0; r < 4; r++) acc[mt][j][r] = 0.f;
    float mm[2][2] = {{-1e30f, -1e30f}, {-1e30f, -1e30f}};
    float ll[2][2] = {{0.f, 0.f}, {0.f, 0.f}};

    const uint32_t fLane = (uint32_t)((lane & 7) + ((lane >> 4) & 1) * 8) * AROW
                         + ((lane >> 3) & 1) * 16;
    const uint32_t qLane = (uint32_t)((lane & 7) + ((lane >> 3) & 1) * 8) * AROW
                         + ((lane >> 4) & 1) * 16;
    const uint32_t bones = (g == 0) ? 0x3C003C00u : 0u;   // B[k][n]=1 at n==0

    for (int kt = 0; kt < 16; kt++) {
        CP_WAIT(0);
        __syncthreads();
        if (kt < 15) issue(kt + 1, (kt + 1) & 1);

        const uint32_t kOff = sbase + SM_RING + (kt & 1) * ABUF + fLane;
        const uint32_t vOff = kOff + 2 * ATILE;

#pragma unroll
        for (int mt = 0; mt < 2; mt++) {
            const uint32_t qOff = sbase + (uint32_t)(wid * 32 + mt * 16) * AROW + qLane;

            // ---- scores (log2 domain), fp16 3-term ----
            float c[8][4];
#pragma unroll
            for (int j = 0; j < 8; j++)
#pragma unroll
                for (int r = 0; r < 4; r++) c[j][r] = 0.f;

#pragma unroll
            for (int ks = 0; ks < 4; ks++) {
                uint32_t qh[4], ql[4];
                ldsm4(qh, qOff + ks * 32);
                ldsm4(ql, qOff + QTILE + ks * 32);
                uint32_t bh[4][4], bl[4][4];
#pragma unroll
                for (int p = 0; p < 4; p++) {
                    ldsm4(bh[p], kOff + p * 16 * AROW + ks * 32);
                    ldsm4(bl[p], kOff + ATILE + p * 16 * AROW + ks * 32);
                }
#pragma unroll
                for (int p = 0; p < 4; p++) {
                    mma_f16(c[2 * p],     qh, bh[p][0], bh[p][1]);
                    mma_f16(c[2 * p + 1], qh, bh[p][2], bh[p][3]);
                }
#pragma unroll
                for (int p = 0; p < 4; p++) {
                    mma_f16(c[2 * p],     qh, bl[p][0], bl[p][1]);
                    mma_f16(c[2 * p + 1], qh, bl[p][2], bl[p][3]);
                }
#pragma unroll
                for (int p = 0; p < 4; p++) {
                    mma_f16(c[2 * p],     ql, bh[p][0], bh[p][1]);
                    mma_f16(c[2 * p + 1], ql, bh[p][2], bh[p][3]);
                }
            }

            // ---- online softmax: max in fp32, p via ex2.approx.f16x2 ----
            float mx0 = -1e30f, mx1 = -1e30f;
#pragma unroll
            for (int j = 0; j < 8; j++) {
                mx0 = fmaxf(mx0, fmaxf(c[j][0], c[j][1]));
                mx1 = fmaxf(mx1, fmaxf(c[j][2], c[j][3]));
            }
            mx0 = fmaxf(mx0, __shfl_xor_sync(0xffffffffu, mx0, 1));
            mx0 = fmaxf(mx0, __shfl_xor_sync(0xffffffffu, mx0, 2));
            mx1 = fmaxf(mx1, __shfl_xor_sync(0xffffffffu, mx1, 1));
            mx1 = fmaxf(mx1, __shfl_xor_sync(0xffffffffu, mx1, 2));
            float mn0 = fmaxf(mm[mt][0], mx0), mn1 = fmaxf(mm[mt][1], mx1);
            float cr0 = exp2f(mm[mt][0] - mn0), cr1 = exp2f(mm[mt][1] - mn1);

            uint32_t p01[8], p23[8];
#pragma unroll
            for (int j = 0; j < 8; j++) {
                p01[j] = ex2_h2(packh2(c[j][0] - mn0, c[j][1] - mn0));
                p23[j] = ex2_h2(packh2(c[j][2] - mn1, c[j][3] - mn1));
            }

#pragma unroll
            for (int j = 0; j < 8; j++) {
                acc[mt][j][0] *= cr0; acc[mt][j][1] *= cr0;
                acc[mt][j][2] *= cr1; acc[mt][j][3] *= cr1;
            }

            // ---- PV + l-sum (ones-column MMA), P and V fp16 ----
            float lsum[4] = {0.f, 0.f, 0.f, 0.f};
#pragma unroll
            for (int ks = 0; ks < 4; ks++) {
                uint32_t ph[4];
                ph[0] = p01[2 * ks];
                ph[1] = p23[2 * ks];
                ph[2] = p01[2 * ks + 1];
                ph[3] = p23[2 * ks + 1];
                mma_f16(lsum, ph, bones, bones);
                uint32_t vh[4][4];
#pragma unroll
                for (int p = 0; p < 4; p++)
                    ldsm4(vh[p], vOff + p * 16 * AROW + ks * 32);
#pragma unroll
                for (int p = 0; p < 4; p++) {
                    mma_f16(acc[mt][2 * p],     ph, vh[p][0], vh[p][1]);
                    mma_f16(acc[mt][2 * p + 1], ph, vh[p][2], vh[p][3]);
                }
            }
            float s0 = __shfl_sync(0xffffffffu, lsum[0], lane & ~3);
            float s1 = __shfl_sync(0xffffffffu, lsum[2], lane & ~3);
            ll[mt][0] = ll[mt][0] * cr0 + s0;
            ll[mt][1] = ll[mt][1] * cr1 + s1;
            mm[mt][0] = mn0; mm[mt][1] = mn1;
        }
    }

    // ---- epilogue: O = acc/l, write fp16 hi/lo ----
#pragma unroll
    for (int mt = 0; mt < 2; mt++) {
        float i0 = 1.f / ll[mt][0], i1 = 1.f / ll[mt][1];
        size_t rg = qrow0 + wid * 32 + mt * 16 + g;
#pragma unroll
        for (int j = 0; j < 8; j++) {
            int col = h * 64 + j * 8 + 2 * tig;
            uint32_t hh, lw;
            split2(acc[mt][j][0] * i0, acc[mt][j][1] * i0, hh, lw);
            *(uint32_t*)(g_Oh + rg * EE + col) = hh;
            *(uint32_t*)(g_Ol + rg * EE + col) = lw;
            split2(acc[mt][j][2] * i1, acc[mt][j][3] * i1, hh, lw);
            *(uint32_t*)(g_Oh + (rg + 8) * EE + col) = hh;
            *(uint32_t*)(g_Ol + (rg + 8) * EE + col) = lw;
        }
    }
}

// ---------------- LayerNorm ----------------
__global__ __launch_bounds__(256) void ln_kernel(
    const float* __restrict__ gamma, const float* __restrict__ beta,
    float* __restrict__ out)
{
    const int row = blockIdx.x;
    const int tid = threadIdx.x;
    const float4 v = *(const float4*)(g_R + (size_t)row * EE + tid * 4);

    float s1 = v.x + v.y + v.z + v.w;
    float s2 = v.x * v.x + v.y * v.y + v.z * v.z + v.w * v.w;

    __shared__ float sh1[8], sh2[8];
#pragma unroll
    for (int off = 16; off > 0; off >>= 1) {
        s1 += __shfl_xor_sync(0xffffffffu, s1, off);
        s2 += __shfl_xor_sync(0xffffffffu, s2, off);
    }
    const int warp = tid >> 5;
    if ((tid & 31) == 0) { sh1[warp] = s1; sh2[warp] = s2; }
    __syncthreads();
    float t1 = 0.f, t2 = 0.f;
#pragma unroll
    for (int w = 0; w < 8; w++) { t1 += sh1[w]; t2 += sh2[w]; }

    const float mean = t1 * (1.0f / EE);
    const float var  = t2 * (1.0f / EE) - mean * mean;
    const float inv  = rsqrtf(var + 1e-6f);

    const float4 gmv = *(const float4*)(gamma + tid * 4);
    const float4 btv = *(const float4*)(beta + tid * 4);
    float4 o;
    o.x = (v.x - mean) * inv * gmv.x + btv.x;
    o.y = (v.y - mean) * inv * gmv.y + btv.y;
    o.z = (v.z - mean) * inv * gmv.z + btv.z;
    o.w = (v.w - mean) * inv * gmv.w + btv.w;
    *(float4*)(out + (size_t)row * EE + tid * 4) = o;
}

// ---------------------------------------------------------------------------
extern "C" void kernel_launch(void* const* d_in, const int* in_sizes, int n_in,
                              void* d_out, int out_size)
{
    const float* X     = (const float*)d_in[0];
    const float* gQ    = (const float*)d_in[1];
    const float* gK    = (const float*)d_in[2];
    const float* Wq    = (const float*)d_in[3];
    const float* Wk    = (const float*)d_in[4];
    const float* Wv    = (const float*)d_in[5];
    const float* Wo    = (const float*)d_in[6];
    const float* gamma = (const float*)d_in[7];
    const float* beta  = (const float*)d_in[8];
    float* out = (float*)d_out;

    cudaFuncSetAttribute(gemm_kernel,
                         cudaFuncAttributeMaxDynamicSharedMemorySize, GEMM_SMEM);
    cudaFuncSetAttribute(attn_kernel,
                         cudaFuncAttributeMaxDynamicSharedMemorySize, ATTN_SMEM);

    prep_x_kernel<<<NELEM / 1024, 256>>>(X);
    prep_w_kernel<<<dim3(32, 32, 4), dim3(32, 8)>>>(Wq, Wk, Wv, Wo);

    gemm_kernel<<<dim3(8, 64, 3), 128, GEMM_SMEM>>>(gQ, gK, X, 0);

    attn_kernel<<<dim3(8, HH, BB), 128, ATTN_SMEM>>>();

    gemm_kernel<<<dim3(8, 64, 1), 128, GEMM_SMEM>>>(gQ, gK, X, 3);
    ln_kernel<<<M_TOT, 256>>>(gamma, beta, out);
}

// round 15
// speedup vs baseline: 1.3094x; 1.0691x over previous
#include <cuda_runtime.h>
#include <cuda_fp16.h>
#include <stdint.h>

#define BB 8
#define SS 1024
#define EE 1024
#define HH 16
#define M_TOT 8192
#define NELEM ((size_t)M_TOT * EE)   /* 8388608 */

// ---------------- scratch (device globals; no allocations) ----------------
__device__ __half g_Xh[NELEM], g_Xl[NELEM];
__device__ __half g_Wth[4 * 1048576], g_Wtl[4 * 1048576];  // [N][K], scaled x32
__device__ __half g_Qh[NELEM], g_Ql[NELEM];   // gate*2*0.125*log2e folded
__device__ __half g_Kh[NELEM], g_Kl[NELEM];   // gate*2 folded
__device__ __half g_Vt[NELEM];                // [(b*H+h)*64+d][s], single fp16
__device__ __half g_Oh[NELEM], g_Ol[NELEM];
__device__ float g_R[NELEM];

// ---------------- helpers ----------------
__device__ __forceinline__ void mma_f16(float* c, const uint32_t* a,
                                        uint32_t b0, uint32_t b1) {
    asm volatile(
        "mma.sync.aligned.m16n8k16.row.col.f32.f16.f16.f32 "
        "{%0,%1,%2,%3}, {%4,%5,%6,%7}, {%8,%9}, {%0,%1,%2,%3};"
        : "+f"(c[0]), "+f"(c[1]), "+f"(c[2]), "+f"(c[3])
        : "r"(a[0]), "r"(a[1]), "r"(a[2]), "r"(a[3]), "r"(b0), "r"(b1));
}

__device__ __forceinline__ void ldsm4(uint32_t* r, uint32_t addr) {
    asm volatile("ldmatrix.sync.aligned.m8n8.x4.shared.b16 {%0,%1,%2,%3}, [%4];"
                 : "=r"(r[0]), "=r"(r[1]), "=r"(r[2]), "=r"(r[3]) : "r"(addr));
}

__device__ __forceinline__ void cp16(uint32_t s, const void* g) {
    asm volatile("cp.async.cg.shared.global [%0], [%1], 16;" :: "r"(s), "l"(g));
}
#define CP_COMMIT asm volatile("cp.async.commit_group;" ::: "memory")
#define CP_WAIT(n) asm volatile("cp.async.wait_group %0;" :: "n"(n) : "memory")

__device__ __forceinline__ uint32_t smem_u32(const void* p) {
    uint32_t a;
    asm("{ .reg .u64 t; cvta.to.shared.u64 t, %1; cvt.u32.u64 %0, t; }"
        : "=r"(a) : "l"(p));
    return a;
}

__device__ __forceinline__ void split2(float x, float y, uint32_t& h, uint32_t& l) {
    __half2 hh = __floats2half2_rn(x, y);
    __half2 ll = __floats2half2_rn(x - __low2float(hh), y - __high2float(hh));
    h = *(uint32_t*)&hh;
    l = *(uint32_t*)&ll;
}

__device__ __forceinline__ uint32_t packh2(float x, float y) {
    __half2 hh = __floats2half2_rn(x, y);
    return *(uint32_t*)&hh;
}

__device__ __forceinline__ uint32_t ex2_h2(uint32_t x) {
    uint32_t r;
    asm("ex2.approx.f16x2 %0, %1;" : "=r"(r) : "r"(x));
    return r;
}

__device__ __forceinline__ void split1(float x, __half& h, __half& l) {
    h = __float2half_rn(x);
    l = __float2half_rn(x - __half2float(h));
}

// ---------------- prep: split X into fp16 hi/lo ----------------
__global__ __launch_bounds__(256) void prep_x_kernel(const float* __restrict__ X)
{
    size_t i = ((size_t)blockIdx.x * 256 + threadIdx.x) * 4;
    float4 v = *(const float4*)(X + i);
    uint32_t h01, l01, h23, l23;
    split2(v.x, v.y, h01, l01);
    split2(v.z, v.w, h23, l23);
    *(uint32_t*)(g_Xh + i)     = h01;
    *(uint32_t*)(g_Xh + i + 2) = h23;
    *(uint32_t*)(g_Xl + i)     = l01;
    *(uint32_t*)(g_Xl + i + 2) = l23;
}

// ---------------- prep: weights x32 -> K-major fp16 hi/lo ----------------
__global__ __launch_bounds__(256) void prep_w_kernel(
    const float* __restrict__ Wq, const float* __restrict__ Wk,
    const float* __restrict__ Wv, const float* __restrict__ Wo)
{
    const int which = blockIdx.z;
    const float* W = (which == 0) ? Wq : (which == 1) ? Wk : (which == 2) ? Wv : Wo;
    __half* Oh = g_Wth + (size_t)which * 1048576;
    __half* Ol = g_Wtl + (size_t)which * 1048576;

    __shared__ float tile[32][33];
    const int tx = threadIdx.x, ty = threadIdx.y;
    const int n0 = blockIdx.x * 32, k0 = blockIdx.y * 32;

    if (which < 3) {
#pragma unroll
        for (int i = 0; i < 4; i++)
            tile[ty + 8 * i][tx] = W[(size_t)(k0 + ty + 8 * i) * EE + n0 + tx];
        __syncthreads();
#pragma unroll
        for (int i = 0; i < 4; i++) {
            float v = tile[tx][ty + 8 * i] * 32.0f;
            __half h, l;
            split1(v, h, l);
            size_t o = (size_t)(n0 + ty + 8 * i) * EE + k0 + tx;
            Oh[o] = h; Ol[o] = l;
        }
    } else {
#pragma unroll
        for (int i = 0; i < 4; i++) {
            size_t o = (size_t)(n0 + ty + 8 * i) * EE + k0 + tx;
            float v = W[o] * 32.0f;
            __half h, l;
            split1(v, h, l);
            Oh[o] = h; Ol[o] = l;
        }
    }
}

// ---------------- GEMM: XOR-swizzled 64B rows, 3-stage, 2 CTAs/SM -----------
// Physical offset of (row r, 16B-chunk c): r*64 + ((c ^ ((r>>1)&3))<<4).
// modes 0,1 (Q,K): 3-term. modes 2,3 (V,out-proj): 1-term (Ah*Bh only).
#define GTILE 8192                         /* 128 rows x 64B */
#define GSTAGE (4 * GTILE)                 /* Ah, Al, Bh, Bl = 32768 */
#define GEMM_SMEM (3 * GSTAGE)             /* 98304 */
#define INV32 0.03125f
#define TSTR 136                           /* V transpose tile row stride (halves) */

__global__ __launch_bounds__(128, 2) void gemm_kernel(
    const float* __restrict__ AuxQ, const float* __restrict__ AuxK,
    const float* __restrict__ AuxX, int modeBase)
{
    extern __shared__ char smb[];
    const uint32_t sbase = smem_u32(smb);

    const int mode = modeBase + blockIdx.z;
    const bool threeTerm = (mode <= 1);
    const __half* Ahp = (mode == 3) ? g_Oh : g_Xh;
    const __half* Alp = (mode == 3) ? g_Ol : g_Xl;
    const __half* Bhp = g_Wth + (size_t)mode * 1048576;
    const __half* Blp = g_Wtl + (size_t)mode * 1048576;

    const int tid = threadIdx.x;
    const int wid = tid >> 5;
    const int lane = tid & 31;
    const int g = lane >> 2;
    const int tig = lane & 3;
    const int wm = wid >> 1;
    const int wn = wid & 1;
    const int colBase = blockIdx.x * 128;
    const int rowBase = blockIdx.y * 128;

    float c[4][8][4];
#pragma unroll
    for (int mt = 0; mt < 4; mt++)
#pragma unroll
        for (int nt = 0; nt < 8; nt++)
#pragma unroll
            for (int r = 0; r < 4; r++) c[mt][nt][r] = 0.f;

    // ldmatrix lane geometry (logical row within 16-row block, chunk-half)
    const int laneRowA = (lane & 7) + ((lane >> 3) & 1) * 8;
    const int hiA = (lane >> 4) & 1;
    const int swA = (laneRowA >> 1) & 3;
    const uint32_t aBaseLane = (uint32_t)(wm * 64 + laneRowA) * 64;
    const int laneRowB = (lane & 7) + ((lane >> 4) & 1) * 8;
    const int hiB = (lane >> 3) & 1;
    const int swB = (laneRowB >> 1) & 3;
    const uint32_t bBaseLane = (uint32_t)(wn * 64 + laneRowB) * 64;

    auto issue = [&](int kt, int stage) {
        uint32_t sb = sbase + stage * GSTAGE;
#pragma unroll
        for (int i = 0; i < 4; i++) {
            int ch = tid + i * 128;
            int r = ch >> 2;
            int cc = ch & 3;
            int c8 = cc * 8;
            uint32_t off = (uint32_t)r * 64 + (uint32_t)((cc ^ ((r >> 1) & 3)) << 4);
            size_t ao = (size_t)(rowBase + r) * EE + kt * 32 + c8;
            cp16(sb + off, Ahp + ao);
            if (threeTerm)
                cp16(sb + GTILE + off, Alp + ao);
        }
#pragma unroll
        for (int i = 0; i < 4; i++) {
            int ch = tid + i * 128;
            int r = ch >> 2;
            int cc = ch & 3;
            int c8 = cc * 8;
            uint32_t off = (uint32_t)r * 64 + (uint32_t)((cc ^ ((r >> 1) & 3)) << 4);
            size_t bo = (size_t)(colBase + r) * EE + kt * 32 + c8;
            cp16(sb + 2 * GTILE + off, Bhp + bo);
            if (threeTerm)
                cp16(sb + 3 * GTILE + off, Blp + bo);
        }
        CP_COMMIT;
    };

    issue(0, 0);
    issue(1, 1);

    for (int kt = 0; kt < 32; kt++) {
        if (kt + 2 < 32) { CP_WAIT(1); } else { CP_WAIT(0); }
        __syncthreads();
        if (kt + 2 < 32) issue(kt + 2, (kt + 2) % 3);

        const uint32_t sb = sbase + (kt % 3) * GSTAGE;

#pragma unroll
        for (int ks = 0; ks < 2; ks++) {
            const uint32_t cA = (uint32_t)(((ks * 2 + hiA) ^ swA) << 4);
            const uint32_t cB = (uint32_t)(((ks * 2 + hiB) ^ swB) << 4);
            uint32_t ah[4][4], bh[4][4];
#pragma unroll
            for (int mt = 0; mt < 4; mt++)
                ldsm4(ah[mt], sb + aBaseLane + mt * 1024 + cA);
#pragma unroll
            for (int p = 0; p < 4; p++)
                ldsm4(bh[p], sb + 2 * GTILE + bBaseLane + p * 1024 + cB);
            // pass 1: Ah*Bh — always
#pragma unroll
            for (int p = 0; p < 4; p++)
#pragma unroll
                for (int mt = 0; mt < 4; mt++) {
                    mma_f16(c[mt][2 * p],     ah[mt], bh[p][0], bh[p][1]);
                    mma_f16(c[mt][2 * p + 1], ah[mt], bh[p][2], bh[p][3]);
                }
            if (threeTerm) {
                // pass 2: Al*Bh
                uint32_t al[4][4];
#pragma unroll
                for (int mt = 0; mt < 4; mt++)
                    ldsm4(al[mt], sb + GTILE + aBaseLane + mt * 1024 + cA);
#pragma unroll
                for (int p = 0; p < 4; p++)
#pragma unroll
                    for (int mt = 0; mt < 4; mt++) {
                        mma_f16(c[mt][2 * p],     al[mt], bh[p][0], bh[p][1]);
                        mma_f16(c[mt][2 * p + 1], al[mt], bh[p][2], bh[p][3]);
                    }
                // pass 3: Ah*Bl
                uint32_t bl[4][4];
#pragma unroll
                for (int p = 0; p < 4; p++)
                    ldsm4(bl[p], sb + 3 * GTILE + bBaseLane + p * 1024 + cB);
#pragma unroll
                for (int p = 0; p < 4; p++)
#pragma unroll
                    for (int mt = 0; mt < 4; mt++) {
                        mma_f16(c[mt][2 * p],     ah[mt], bl[p][0], bl[p][1]);
                        mma_f16(c[mt][2 * p + 1], ah[mt], bl[p][2], bl[p][3]);
                    }
            }
        }
    }

    // ---- epilogues (fold 1/32 from weight scaling) ----
    const int batch = rowBase / SS;
    if (mode <= 1) {
        __half* Oh = (mode == 0) ? g_Qh : g_Kh;
        __half* Ol = (mode == 0) ? g_Ql : g_Kl;
        const float sc = ((mode == 0) ? 0.25f * 1.44269504089f : 2.0f) * INV32;
        const float* Aux = (mode == 0) ? AuxQ : AuxK;
#pragma unroll
        for (int mt = 0; mt < 4; mt++) {
            size_t row0 = (size_t)rowBase + wm * 64 + mt * 16 + g;
#pragma unroll
            for (int nt = 0; nt < 8; nt++) {
                int col = colBase + wn * 64 + nt * 8 + 2 * tig;
                float2 gv = *(const float2*)(Aux + (size_t)batch * EE + col);
                float gx = gv.x * sc, gy = gv.y * sc;
                uint32_t h, l;
                split2(c[mt][nt][0] * gx, c[mt][nt][1] * gy, h, l);
                *(uint32_t*)(Oh + row0 * EE + col) = h;
                *(uint32_t*)(Ol + row0 * EE + col) = l;
                split2(c[mt][nt][2] * gx, c[mt][nt][3] * gy, h, l);
                *(uint32_t*)(Oh + (row0 + 8) * EE + col) = h;
                *(uint32_t*)(Ol + (row0 + 8) * EE + col) = l;
            }
        }
    } else if (mode == 2) {
        // V: transpose through smem, then coalesced stores
        __syncthreads();
        __half* T = (__half*)smb;        // 128 (d) x TSTR
#pragma unroll
        for (int mt = 0; mt < 4; mt++) {
            int row = wm * 64 + mt * 16 + g;     // local s 0..127
#pragma unroll
            for (int nt = 0; nt < 8; nt++) {
                int cl = wn * 64 + nt * 8 + 2 * tig;  // local d 0..127
                T[(size_t)cl * TSTR + row]           = __float2half_rn(c[mt][nt][0] * INV32);
                T[(size_t)(cl + 1) * TSTR + row]     = __float2half_rn(c[mt][nt][1] * INV32);
                T[(size_t)cl * TSTR + row + 8]       = __float2half_rn(c[mt][nt][2] * INV32);
                T[(size_t)(cl + 1) * TSTR + row + 8] = __float2half_rn(c[mt][nt][3] * INV32);
            }
        }
        __syncthreads();
        const int s0 = rowBase & (SS - 1);
        const int dl = tid >> 2;
        const int ch = tid & 3;
#pragma unroll
        for (int pass = 0; pass < 4; pass++) {
            int d = dl + pass * 32;
            int gcol = colBase + d;
            int hh = gcol >> 6, dd = gcol & 63;
            size_t vb = ((size_t)(batch * HH + hh) * 64 + dd) * SS + s0 + ch * 32;
            uint4* dst = (uint4*)(g_Vt + vb);
            const uint4* src = (const uint4*)(T + (size_t)d * TSTR + ch * 32);
            dst[0] = src[0]; dst[1] = src[1]; dst[2] = src[2]; dst[3] = src[3];
        }
    } else {
#pragma unroll
        for (int mt = 0; mt < 4; mt++) {
            size_t row0 = (size_t)rowBase + wm * 64 + mt * 16 + g;
#pragma unroll
            for (int nt = 0; nt < 8; nt++) {
                int col = colBase + wn * 64 + nt * 8 + 2 * tig;
                float2 x0 = *(const float2*)(AuxX + row0 * EE + col);
                float2 x1 = *(const float2*)(AuxX + (row0 + 8) * EE + col);
                *(float2*)(g_R + row0 * EE + col) =
                    make_float2(c[mt][nt][0] * INV32 + x0.x, c[mt][nt][1] * INV32 + x0.y);
                *(float2*)(g_R + (row0 + 8) * EE + col) =
                    make_float2(c[mt][nt][2] * INV32 + x1.x, c[mt][nt][3] * INV32 + x1.y);
            }
        }
    }
}

// ---- flash attention: q-tile 128 (Q in smem), ex2.f16x2 softmax, MMA l-sum ----
#define AROW 144
#define ATILE (64 * AROW)                  /* 9216: one K or V tile */
#define QTILE (128 * AROW)                 /* 18432: Qh or Ql resident */
#define ABUF (3 * ATILE)                   /* Kh, Kl, V = 27648 per stage */
#define SM_RING (2 * QTILE)                /* ring base = 36864 */
#define ATTN_SMEM (2 * QTILE + 2 * ABUF)   /* 92160 */

__global__ __launch_bounds__(128, 2) void attn_kernel()
{
    extern __shared__ char smb[];
    const uint32_t sbase = smem_u32(smb);

    const int qt = blockIdx.x;     // 0..7 (128 q rows each)
    const int h  = blockIdx.y;
    const int b  = blockIdx.z;
    const int tid = threadIdx.x;
    const int wid = tid >> 5;      // 0..3 (32 q rows each)
    const int lane = tid & 31;
    const int g = lane >> 2;
    const int tig = lane & 3;

    const size_t kbase0 = ((size_t)b * SS) * EE + h * 64;
    const size_t vbase0 = ((size_t)(b * HH + h) * 64) * SS;
    const size_t qrow0  = (size_t)(b * SS + qt * 128);

    auto issue = [&](int kt, int stage) {
        uint32_t sb = sbase + SM_RING + stage * ABUF;
#pragma unroll
        for (int i = 0; i < 4; i++) {
            int ch = tid + i * 128;        // 0..511
            int r = ch >> 3;               // 0..63
            int cb = (ch & 7) * 16;
            int c8 = (ch & 7) * 8;
            size_t ko = kbase0 + (size_t)(kt * 64 + r) * EE + c8;
            size_t vo = vbase0 + (size_t)r * SS + kt * 64 + c8;
            uint32_t off = r * AROW + cb;
            cp16(sb + off,             g_Kh + ko);
            cp16(sb + ATILE + off,     g_Kl + ko);
            cp16(sb + 2 * ATILE + off, g_Vt + vo);
        }
        CP_COMMIT;
    };

    // ---- load Q (hi+lo) into resident smem ----
#pragma unroll
    for (int i = 0; i < 8; i++) {
        int ch = tid + i * 128;            // 0..1023
        int r = ch >> 3;                   // 0..127
        int cb = (ch & 7) * 16;
        int c8 = (ch & 7) * 8;
        uint32_t off = r * AROW + cb;
        size_t go = (qrow0 + r) * EE + h * 64 + c8;
        cp16(sbase + off,         g_Qh + go);
        cp16(sbase + QTILE + off, g_Ql + go);
    }
    CP_COMMIT;
    issue(0, 0);

    float acc[2][8][4];
#pragma unroll
    for (int mt = 0; mt < 2; mt++)
#pragma unroll
        for (int j = 0; j < 8; j++)
#pragma unroll
            for (int r = 0; r < 4; r++) acc[mt][j][r] = 0.f;
    float mm[2][2] = {{-1e30f, -1e30f}, {-1e30f, -1e30f}};
    float ll[2][2] = {{0.f, 0.f}, {0.f, 0.f}};

    const uint32_t fLane = (uint32_t)((lane & 7) + ((lane >> 4) & 1) * 8) * AROW
                         + ((lane >> 3) & 1) * 16;
    const uint32_t qLane = (uint32_t)((lane & 7) + ((lane >> 3) & 1) * 8) * AROW
                         + ((lane >> 4) & 1) * 16;
    const uint32_t bones = (g == 0) ? 0x3C003C00u : 0u;   // B[k][n]=1 at n==0

    for (int kt = 0; kt < 16; kt++) {
        CP_WAIT(0);
        __syncthreads();
        if (kt < 15) issue(kt + 1, (kt + 1) & 1);

        const uint32_t kOff = sbase + SM_RING + (kt & 1) * ABUF + fLane;
        const uint32_t vOff = kOff + 2 * ATILE;

#pragma unroll
        for (int mt = 0; mt < 2; mt++) {
            const uint32_t qOff = sbase + (uint32_t)(wid * 32 + mt * 16) * AROW + qLane;

            // ---- scores (log2 domain), fp16 3-term ----
            float c[8][4];
#pragma unroll
            for (int j = 0; j < 8; j++)
#pragma unroll
                for (int r = 0; r < 4; r++) c[j][r] = 0.f;

#pragma unroll
            for (int ks = 0; ks < 4; ks++) {
                uint32_t qh[4], ql[4];
                ldsm4(qh, qOff + ks * 32);
                ldsm4(ql, qOff + QTILE + ks * 32);
                uint32_t bh[4][4], bl[4][4];
#pragma unroll
                for (int p = 0; p < 4; p++) {
                    ldsm4(bh[p], kOff + p * 16 * AROW + ks * 32);
                    ldsm4(bl[p], kOff + ATILE + p * 16 * AROW + ks * 32);
                }
#pragma unroll
                for (int p = 0; p < 4; p++) {
                    mma_f16(c[2 * p],     qh, bh[p][0], bh[p][1]);
                    mma_f16(c[2 * p + 1], qh, bh[p][2], bh[p][3]);
                }
#pragma unroll
                for (int p = 0; p < 4; p++) {
                    mma_f16(c[2 * p],     qh, bl[p][0], bl[p][1]);
                    mma_f16(c[2 * p + 1], qh, bl[p][2], bl[p][3]);
                }
#pragma unroll
                for (int p = 0; p < 4; p++) {
                    mma_f16(c[2 * p],     ql, bh[p][0], bh[p][1]);
                    mma_f16(c[2 * p + 1], ql, bh[p][2], bh[p][3]);
                }
            }

            // ---- online softmax: max in fp32, p via ex2.approx.f16x2 ----
            float mx0 = -1e30f, mx1 = -1e30f;
#pragma unroll
            for (int j = 0; j < 8; j++) {
                mx0 = fmaxf(mx0, fmaxf(c[j][0], c[j][1]));
                mx1 = fmaxf(mx1, fmaxf(c[j][2], c[j][3]));
            }
            mx0 = fmaxf(mx0, __shfl_xor_sync(0xffffffffu, mx0, 1));
            mx0 = fmaxf(mx0, __shfl_xor_sync(0xffffffffu, mx0, 2));
            mx1 = fmaxf(mx1, __shfl_xor_sync(0xffffffffu, mx1, 1));
            mx1 = fmaxf(mx1, __shfl_xor_sync(0xffffffffu, mx1, 2));
            float mn0 = fmaxf(mm[mt][0], mx0), mn1 = fmaxf(mm[mt][1], mx1);
            float cr0 = exp2f(mm[mt][0] - mn0), cr1 = exp2f(mm[mt][1] - mn1);

            uint32_t p01[8], p23[8];
#pragma unroll
            for (int j = 0; j < 8; j++) {
                p01[j] = ex2_h2(packh2(c[j][0] - mn0, c[j][1] - mn0));
                p23[j] = ex2_h2(packh2(c[j][2] - mn1, c[j][3] - mn1));
            }

#pragma unroll
            for (int j = 0; j < 8; j++) {
                acc[mt][j][0] *= cr0; acc[mt][j][1] *= cr0;
                acc[mt][j][2] *= cr1; acc[mt][j][3] *= cr1;
            }

            // ---- PV + l-sum (ones-column MMA), P and V fp16 ----
            float lsum[4] = {0.f, 0.f, 0.f, 0.f};
#pragma unroll
            for (int ks = 0; ks < 4; ks++) {
                uint32_t ph[4];
                ph[0] = p01[2 * ks];
                ph[1] = p23[2 * ks];
                ph[2] = p01[2 * ks + 1];
                ph[3] = p23[2 * ks + 1];
                mma_f16(lsum, ph, bones, bones);
                uint32_t vh[4][4];
#pragma unroll
                for (int p = 0; p < 4; p++)
                    ldsm4(vh[p], vOff + p * 16 * AROW + ks * 32);
#pragma unroll
                for (int p = 0; p < 4; p++) {
                    mma_f16(acc[mt][2 * p],     ph, vh[p][0], vh[p][1]);
                    mma_f16(acc[mt][2 * p + 1], ph, vh[p][2], vh[p][3]);
                }
            }
            float s0 = __shfl_sync(0xffffffffu, lsum[0], lane & ~3);
            float s1 = __shfl_sync(0xffffffffu, lsum[2], lane & ~3);
            ll[mt][0] = ll[mt][0] * cr0 + s0;
            ll[mt][1] = ll[mt][1] * cr1 + s1;
            mm[mt][0] = mn0; mm[mt][1] = mn1;
        }
    }

    // ---- epilogue: O = acc/l, write fp16 hi/lo ----
#pragma unroll
    for (int mt = 0; mt < 2; mt++) {
        float i0 = 1.f / ll[mt][0], i1 = 1.f / ll[mt][1];
        size_t rg = qrow0 + wid * 32 + mt * 16 + g;
#pragma unroll
        for (int j = 0; j < 8; j++) {
            int col = h * 64 + j * 8 + 2 * tig;
            uint32_t hh, lw;
            split2(acc[mt][j][0] * i0, acc[mt][j][1] * i0, hh, lw);
            *(uint32_t*)(g_Oh + rg * EE + col) = hh;
            *(uint32_t*)(g_Ol + rg * EE + col) = lw;
            split2(acc[mt][j][2] * i1, acc[mt][j][3] * i1, hh, lw);
            *(uint32_t*)(g_Oh + (rg + 8) * EE + col) = hh;
            *(uint32_t*)(g_Ol + (rg + 8) * EE + col) = lw;
        }
    }
}

// ---------------- LayerNorm ----------------
__global__ __launch_bounds__(256) void ln_kernel(
    const float* __restrict__ gamma, const float* __restrict__ beta,
    float* __restrict__ out)
{
    const int row = blockIdx.x;
    const int tid = threadIdx.x;
    const float4 v = *(const float4*)(g_R + (size_t)row * EE + tid * 4);

    float s1 = v.x + v.y + v.z + v.w;
    float s2 = v.x * v.x + v.y * v.y + v.z * v.z + v.w * v.w;

    __shared__ float sh1[8], sh2[8];
#pragma unroll
    for (int off = 16; off > 0; off >>= 1) {
        s1 += __shfl_xor_sync(0xffffffffu, s1, off);
        s2 += __shfl_xor_sync(0xffffffffu, s2, off);
    }
    const int warp = tid >> 5;
    if ((tid & 31) == 0) { sh1[warp] = s1; sh2[warp] = s2; }
    __syncthreads();
    float t1 = 0.f, t2 = 0.f;
#pragma unroll
    for (int w = 0; w < 8; w++) { t1 += sh1[w]; t2 += sh2[w]; }

    const float mean = t1 * (1.0f / EE);
    const float var  = t2 * (1.0f / EE) - mean * mean;
    const float inv  = rsqrtf(var + 1e-6f);

    const float4 gmv = *(const float4*)(gamma + tid * 4);
    const float4 btv = *(const float4*)(beta + tid * 4);
    float4 o;
    o.x = (v.x - mean) * inv * gmv.x + btv.x;
    o.y = (v.y - mean) * inv * gmv.y + btv.y;
    o.z = (v.z - mean) * inv * gmv.z + btv.z;
    o.w = (v.w - mean) * inv * gmv.w + btv.w;
    *(float4*)(out + (size_t)row * EE + tid * 4) = o;
}

// ---------------------------------------------------------------------------
extern "C" void kernel_launch(void* const* d_in, const int* in_sizes, int n_in,
                              void* d_out, int out_size)
{
    const float* X     = (const float*)d_in[0];
    const float* gQ    = (const float*)d_in[1];
    const float* gK    = (const float*)d_in[2];
    const float* Wq    = (const float*)d_in[3];
    const float* Wk    = (const float*)d_in[4];
    const float* Wv    = (const float*)d_in[5];
    const float* Wo    = (const float*)d_in[6];
    const float* gamma = (const float*)d_in[7];
    const float* beta  = (const float*)d_in[8];
    float* out = (float*)d_out;

    cudaFuncSetAttribute(gemm_kernel,
                         cudaFuncAttributeMaxDynamicSharedMemorySize, GEMM_SMEM);
    cudaFuncSetAttribute(attn_kernel,
                         cudaFuncAttributeMaxDynamicSharedMemorySize, ATTN_SMEM);

    prep_x_kernel<<<NELEM / 1024, 256>>>(X);
    prep_w_kernel<<<dim3(32, 32, 4), dim3(32, 8)>>>(Wq, Wk, Wv, Wo);

    gemm_kernel<<<dim3(8, 64, 3), 128, GEMM_SMEM>>>(gQ, gK, X, 0);

    attn_kernel<<<dim3(8, HH, BB), 128, ATTN_SMEM>>>();

    gemm_kernel<<<dim3(8, 64, 1), 128, GEMM_SMEM>>>(gQ, gK, X, 3);
    ln_kernel<<<M_TOT, 256>>>(gamma, beta, out);
}

// round 16
// speedup vs baseline: 1.4954x; 1.1420x over previous
#include <cuda_runtime.h>
#include <cuda_fp16.h>
#include <stdint.h>

#define BB 8
#define SS 1024
#define EE 1024
#define HH 16
#define M_TOT 8192
#define NELEM ((size_t)M_TOT * EE)   /* 8388608 */

// ---------------- scratch (device globals; no allocations) ----------------
__device__ __half g_Xh[NELEM], g_Xl[NELEM];
__device__ __half g_Wth[4 * 1048576];         // [N][K], scaled x32 (hi only)
__device__ __half g_Qh[NELEM], g_Ql[NELEM];   // gate*2*0.125*log2e folded
__device__ __half g_Kh[NELEM], g_Kl[NELEM];   // gate*2 folded
__device__ __half g_Vt[NELEM];                // [(b*H+h)*64+d][s], single fp16
__device__ __half g_Oh[NELEM];                // attention output, single fp16
__device__ float g_R[NELEM];

// ---------------- helpers ----------------
__device__ __forceinline__ void mma_f16(float* c, const uint32_t* a,
                                        uint32_t b0, uint32_t b1) {
    asm volatile(
        "mma.sync.aligned.m16n8k16.row.col.f32.f16.f16.f32 "
        "{%0,%1,%2,%3}, {%4,%5,%6,%7}, {%8,%9}, {%0,%1,%2,%3};"
        : "+f"(c[0]), "+f"(c[1]), "+f"(c[2]), "+f"(c[3])
        : "r"(a[0]), "r"(a[1]), "r"(a[2]), "r"(a[3]), "r"(b0), "r"(b1));
}

__device__ __forceinline__ void ldsm4(uint32_t* r, uint32_t addr) {
    asm volatile("ldmatrix.sync.aligned.m8n8.x4.shared.b16 {%0,%1,%2,%3}, [%4];"
                 : "=r"(r[0]), "=r"(r[1]), "=r"(r[2]), "=r"(r[3]) : "r"(addr));
}

__device__ __forceinline__ void cp16(uint32_t s, const void* g) {
    asm volatile("cp.async.cg.shared.global [%0], [%1], 16;" :: "r"(s), "l"(g));
}
#define CP_COMMIT asm volatile("cp.async.commit_group;" ::: "memory")
#define CP_WAIT(n) asm volatile("cp.async.wait_group %0;" :: "n"(n) : "memory")

__device__ __forceinline__ uint32_t smem_u32(const void* p) {
    uint32_t a;
    asm("{ .reg .u64 t; cvta.to.shared.u64 t, %1; cvt.u32.u64 %0, t; }"
        : "=r"(a) : "l"(p));
    return a;
}

__device__ __forceinline__ void split2(float x, float y, uint32_t& h, uint32_t& l) {
    __half2 hh = __floats2half2_rn(x, y);
    __half2 ll = __floats2half2_rn(x - __low2float(hh), y - __high2float(hh));
    h = *(uint32_t*)&hh;
    l = *(uint32_t*)&ll;
}

__device__ __forceinline__ uint32_t packh2(float x, float y) {
    __half2 hh = __floats2half2_rn(x, y);
    return *(uint32_t*)&hh;
}

__device__ __forceinline__ uint32_t ex2_h2(uint32_t x) {
    uint32_t r;
    asm("ex2.approx.f16x2 %0, %1;" : "=r"(r) : "r"(x));
    return r;
}

// ---------------- prep: split X into fp16 hi/lo ----------------
__global__ __launch_bounds__(256) void prep_x_kernel(const float* __restrict__ X)
{
    size_t i = ((size_t)blockIdx.x * 256 + threadIdx.x) * 4;
    float4 v = *(const float4*)(X + i);
    uint32_t h01, l01, h23, l23;
    split2(v.x, v.y, h01, l01);
    split2(v.z, v.w, h23, l23);
    *(uint32_t*)(g_Xh + i)     = h01;
    *(uint32_t*)(g_Xh + i + 2) = h23;
    *(uint32_t*)(g_Xl + i)     = l01;
    *(uint32_t*)(g_Xl + i + 2) = l23;
}

// ---------------- prep: weights x32 -> K-major fp16 (hi only) ----------------
__global__ __launch_bounds__(256) void prep_w_kernel(
    const float* __restrict__ Wq, const float* __restrict__ Wk,
    const float* __restrict__ Wv, const float* __restrict__ Wo)
{
    const int which = blockIdx.z;
    const float* W = (which == 0) ? Wq : (which == 1) ? Wk : (which == 2) ? Wv : Wo;
    __half* Oh = g_Wth + (size_t)which * 1048576;

    __shared__ float tile[32][33];
    const int tx = threadIdx.x, ty = threadIdx.y;
    const int n0 = blockIdx.x * 32, k0 = blockIdx.y * 32;

    if (which < 3) {
#pragma unroll
        for (int i = 0; i < 4; i++)
            tile[ty + 8 * i][tx] = W[(size_t)(k0 + ty + 8 * i) * EE + n0 + tx];
        __syncthreads();
#pragma unroll
        for (int i = 0; i < 4; i++) {
            float v = tile[tx][ty + 8 * i] * 32.0f;
            Oh[(size_t)(n0 + ty + 8 * i) * EE + k0 + tx] = __float2half_rn(v);
        }
    } else {
#pragma unroll
        for (int i = 0; i < 4; i++) {
            size_t o = (size_t)(n0 + ty + 8 * i) * EE + k0 + tx;
            Oh[o] = __float2half_rn(W[o] * 32.0f);
        }
    }
}

// ---------------- GEMM: XOR-swizzled 64B rows, 4-stage, 2 CTAs/SM -----------
// Physical offset of (row r, 16B-chunk c): r*64 + ((c ^ ((r>>1)&3))<<4).
// modes 0,1 (Q,K): 2-term (Ah*Bh + Al*Bh). modes 2,3 (V,out-proj): 1-term.
#define GTILE 8192                         /* 128 rows x 64B */
#define GSTAGE (3 * GTILE)                 /* Ah, Al, Bh = 24576 */
#define GEMM_SMEM (4 * GSTAGE)             /* 98304 */
#define INV32 0.03125f
#define TSTR 136                           /* V transpose tile row stride (halves) */

__global__ __launch_bounds__(128, 2) void gemm_kernel(
    const float* __restrict__ AuxQ, const float* __restrict__ AuxK,
    const float* __restrict__ AuxX, int modeBase)
{
    extern __shared__ char smb[];
    const uint32_t sbase = smem_u32(smb);

    const int mode = modeBase + blockIdx.z;
    const bool twoTerm = (mode <= 1);
    const __half* Ahp = (mode == 3) ? g_Oh : g_Xh;
    const __half* Alp = g_Xl;              // only used for modes 0,1
    const __half* Bhp = g_Wth + (size_t)mode * 1048576;

    const int tid = threadIdx.x;
    const int wid = tid >> 5;
    const int lane = tid & 31;
    const int g = lane >> 2;
    const int tig = lane & 3;
    const int wm = wid >> 1;
    const int wn = wid & 1;
    const int colBase = blockIdx.x * 128;
    const int rowBase = blockIdx.y * 128;

    float c[4][8][4];
#pragma unroll
    for (int mt = 0; mt < 4; mt++)
#pragma unroll
        for (int nt = 0; nt < 8; nt++)
#pragma unroll
            for (int r = 0; r < 4; r++) c[mt][nt][r] = 0.f;

    // ldmatrix lane geometry
    const int laneRowA = (lane & 7) + ((lane >> 3) & 1) * 8;
    const int hiA = (lane >> 4) & 1;
    const int swA = (laneRowA >> 1) & 3;
    const uint32_t aBaseLane = (uint32_t)(wm * 64 + laneRowA) * 64;
    const int laneRowB = (lane & 7) + ((lane >> 4) & 1) * 8;
    const int hiB = (lane >> 3) & 1;
    const int swB = (laneRowB >> 1) & 3;
    const uint32_t bBaseLane = (uint32_t)(wn * 64 + laneRowB) * 64;

    auto issue = [&](int kt, int stage) {
        uint32_t sb = sbase + stage * GSTAGE;
#pragma unroll
        for (int i = 0; i < 4; i++) {
            int ch = tid + i * 128;
            int r = ch >> 2;
            int cc = ch & 3;
            int c8 = cc * 8;
            uint32_t off = (uint32_t)r * 64 + (uint32_t)((cc ^ ((r >> 1) & 3)) << 4);
            size_t ao = (size_t)(rowBase + r) * EE + kt * 32 + c8;
            cp16(sb + off, Ahp + ao);
            if (twoTerm)
                cp16(sb + GTILE + off, Alp + ao);
            size_t bo = (size_t)(colBase + r) * EE + kt * 32 + c8;
            cp16(sb + 2 * GTILE + off, Bhp + bo);
        }
        CP_COMMIT;
    };

    issue(0, 0);
    issue(1, 1);
    issue(2, 2);

    for (int kt = 0; kt < 32; kt++) {
        if (kt < 30) { CP_WAIT(2); }
        else if (kt == 30) { CP_WAIT(1); }
        else { CP_WAIT(0); }
        __syncthreads();
        if (kt + 3 < 32) issue(kt + 3, (kt + 3) & 3);

        const uint32_t sb = sbase + (kt & 3) * GSTAGE;

#pragma unroll
        for (int ks = 0; ks < 2; ks++) {
            const uint32_t cA = (uint32_t)(((ks * 2 + hiA) ^ swA) << 4);
            const uint32_t cB = (uint32_t)(((ks * 2 + hiB) ^ swB) << 4);
            uint32_t ah[4][4], bh[4][4];
#pragma unroll
            for (int mt = 0; mt < 4; mt++)
                ldsm4(ah[mt], sb + aBaseLane + mt * 1024 + cA);
#pragma unroll
            for (int p = 0; p < 4; p++)
                ldsm4(bh[p], sb + 2 * GTILE + bBaseLane + p * 1024 + cB);
            // pass 1: Ah*Bh — always
#pragma unroll
            for (int p = 0; p < 4; p++)
#pragma unroll
                for (int mt = 0; mt < 4; mt++) {
                    mma_f16(c[mt][2 * p],     ah[mt], bh[p][0], bh[p][1]);
                    mma_f16(c[mt][2 * p + 1], ah[mt], bh[p][2], bh[p][3]);
                }
            if (twoTerm) {
                // pass 2: Al*Bh
                uint32_t al[4][4];
#pragma unroll
                for (int mt = 0; mt < 4; mt++)
                    ldsm4(al[mt], sb + GTILE + aBaseLane + mt * 1024 + cA);
#pragma unroll
                for (int p = 0; p < 4; p++)
#pragma unroll
                    for (int mt = 0; mt < 4; mt++) {
                        mma_f16(c[mt][2 * p],     al[mt], bh[p][0], bh[p][1]);
                        mma_f16(c[mt][2 * p + 1], al[mt], bh[p][2], bh[p][3]);
                    }
            }
        }
    }

    // ---- epilogues (fold 1/32 from weight scaling) ----
    const int batch = rowBase / SS;
    if (mode <= 1) {
        __half* Oh = (mode == 0) ? g_Qh : g_Kh;
        __half* Ol = (mode == 0) ? g_Ql : g_Kl;
        const float sc = ((mode == 0) ? 0.25f * 1.44269504089f : 2.0f) * INV32;
        const float* Aux = (mode == 0) ? AuxQ : AuxK;
#pragma unroll
        for (int mt = 0; mt < 4; mt++) {
            size_t row0 = (size_t)rowBase + wm * 64 + mt * 16 + g;
#pragma unroll
            for (int nt = 0; nt < 8; nt++) {
                int col = colBase + wn * 64 + nt * 8 + 2 * tig;
                float2 gv = *(const float2*)(Aux + (size_t)batch * EE + col);
                float gx = gv.x * sc, gy = gv.y * sc;
                uint32_t h, l;
                split2(c[mt][nt][0] * gx, c[mt][nt][1] * gy, h, l);
                *(uint32_t*)(Oh + row0 * EE + col) = h;
                *(uint32_t*)(Ol + row0 * EE + col) = l;
                split2(c[mt][nt][2] * gx, c[mt][nt][3] * gy, h, l);
                *(uint32_t*)(Oh + (row0 + 8) * EE + col) = h;
                *(uint32_t*)(Ol + (row0 + 8) * EE + col) = l;
            }
        }
    } else if (mode == 2) {
        // V: transpose through smem, then coalesced stores
        __syncthreads();
        __half* T = (__half*)smb;        // 128 (d) x TSTR
#pragma unroll
        for (int mt = 0; mt < 4; mt++) {
            int row = wm * 64 + mt * 16 + g;     // local s 0..127
#pragma unroll
            for (int nt = 0; nt < 8; nt++) {
                int cl = wn * 64 + nt * 8 + 2 * tig;  // local d 0..127
                T[(size_t)cl * TSTR + row]           = __float2half_rn(c[mt][nt][0] * INV32);
                T[(size_t)(cl + 1) * TSTR + row]     = __float2half_rn(c[mt][nt][1] * INV32);
                T[(size_t)cl * TSTR + row + 8]       = __float2half_rn(c[mt][nt][2] * INV32);
                T[(size_t)(cl + 1) * TSTR + row + 8] = __float2half_rn(c[mt][nt][3] * INV32);
            }
        }
        __syncthreads();
        const int s0 = rowBase & (SS - 1);
        const int dl = tid >> 2;
        const int ch = tid & 3;
#pragma unroll
        for (int pass = 0; pass < 4; pass++) {
            int d = dl + pass * 32;
            int gcol = colBase + d;
            int hh = gcol >> 6, dd = gcol & 63;
            size_t vb = ((size_t)(batch * HH + hh) * 64 + dd) * SS + s0 + ch * 32;
            uint4* dst = (uint4*)(g_Vt + vb);
            const uint4* src = (const uint4*)(T + (size_t)d * TSTR + ch * 32);
            dst[0] = src[0]; dst[1] = src[1]; dst[2] = src[2]; dst[3] = src[3];
        }
    } else {
#pragma unroll
        for (int mt = 0; mt < 4; mt++) {
            size_t row0 = (size_t)rowBase + wm * 64 + mt * 16 + g;
#pragma unroll
            for (int nt = 0; nt < 8; nt++) {
                int col = colBase + wn * 64 + nt * 8 + 2 * tig;
                float2 x0 = *(const float2*)(AuxX + row0 * EE + col);
                float2 x1 = *(const float2*)(AuxX + (row0 + 8) * EE + col);
                *(float2*)(g_R + row0 * EE + col) =
                    make_float2(c[mt][nt][0] * INV32 + x0.x, c[mt][nt][1] * INV32 + x0.y);
                *(float2*)(g_R + (row0 + 8) * EE + col) =
                    make_float2(c[mt][nt][2] * INV32 + x1.x, c[mt][nt][3] * INV32 + x1.y);
            }
        }
    }
}

// ---- flash attention: q-tile 128 (Q in smem), ex2.f16x2 softmax, MMA l-sum ----
#define AROW 144
#define ATILE (64 * AROW)                  /* 9216: one K or V tile */
#define QTILE (128 * AROW)                 /* 18432: Qh or Ql resident */
#define ABUF (3 * ATILE)                   /* Kh, Kl, V = 27648 per stage */
#define SM_RING (2 * QTILE)                /* ring base = 36864 */
#define ATTN_SMEM (2 * QTILE + 2 * ABUF)   /* 92160 */

__global__ __launch_bounds__(128, 2) void attn_kernel()
{
    extern __shared__ char smb[];
    const uint32_t sbase = smem_u32(smb);

    const int qt = blockIdx.x;     // 0..7 (128 q rows each)
    const int h  = blockIdx.y;
    const int b  = blockIdx.z;
    const int tid = threadIdx.x;
    const int wid = tid >> 5;      // 0..3 (32 q rows each)
    const int lane = tid & 31;
    const int g = lane >> 2;
    const int tig = lane & 3;

    const size_t kbase0 = ((size_t)b * SS) * EE + h * 64;
    const size_t vbase0 = ((size_t)(b * HH + h) * 64) * SS;
    const size_t qrow0  = (size_t)(b * SS + qt * 128);

    auto issue = [&](int kt, int stage) {
        uint32_t sb = sbase + SM_RING + stage * ABUF;
#pragma unroll
        for (int i = 0; i < 4; i++) {
            int ch = tid + i * 128;        // 0..511
            int r = ch >> 3;               // 0..63
            int cb = (ch & 7) * 16;
            int c8 = (ch & 7) * 8;
            size_t ko = kbase0 + (size_t)(kt * 64 + r) * EE + c8;
            size_t vo = vbase0 + (size_t)r * SS + kt * 64 + c8;
            uint32_t off = r * AROW + cb;
            cp16(sb + off,             g_Kh + ko);
            cp16(sb + ATILE + off,     g_Kl + ko);
            cp16(sb + 2 * ATILE + off, g_Vt + vo);
        }
        CP_COMMIT;
    };

    // ---- load Q (hi+lo) into resident smem ----
#pragma unroll
    for (int i = 0; i < 8; i++) {
        int ch = tid + i * 128;            // 0..1023
        int r = ch >> 3;                   // 0..127
        int cb = (ch & 7) * 16;
        int c8 = (ch & 7) * 8;
        uint32_t off = r * AROW + cb;
        size_t go = (qrow0 + r) * EE + h * 64 + c8;
        cp16(sbase + off,         g_Qh + go);
        cp16(sbase + QTILE + off, g_Ql + go);
    }
    CP_COMMIT;
    issue(0, 0);

    float acc[2][8][4];
#pragma unroll
    for (int mt = 0; mt < 2; mt++)
#pragma unroll
        for (int j = 0; j < 8; j++)
#pragma unroll
            for (int r = 0; r < 4; r++) acc[mt][j][r] = 0.f;
    float mm[2][2] = {{-1e30f, -1e30f}, {-1e30f, -1e30f}};
    float ll[2][2] = {{0.f, 0.f}, {0.f, 0.f}};

    const uint32_t fLane = (uint32_t)((lane & 7) + ((lane >> 4) & 1) * 8) * AROW
                         + ((lane >> 3) & 1) * 16;
    const uint32_t qLane = (uint32_t)((lane & 7) + ((lane >> 3) & 1) * 8) * AROW
                         + ((lane >> 4) & 1) * 16;
    const uint32_t bones = (g == 0) ? 0x3C003C00u : 0u;   // B[k][n]=1 at n==0

    for (int kt = 0; kt < 16; kt++) {
        CP_WAIT(0);
        __syncthreads();
        if (kt < 15) issue(kt + 1, (kt + 1) & 1);

        const uint32_t kOff = sbase + SM_RING + (kt & 1) * ABUF + fLane;
        const uint32_t vOff = kOff + 2 * ATILE;

#pragma unroll
        for (int mt = 0; mt < 2; mt++) {
            const uint32_t qOff = sbase + (uint32_t)(wid * 32 + mt * 16) * AROW + qLane;

            // ---- scores (log2 domain), fp16 3-term ----
            float c[8][4];
#pragma unroll
            for (int j = 0; j < 8; j++)
#pragma unroll
                for (int r = 0; r < 4; r++) c[j][r] = 0.f;

#pragma unroll
            for (int ks = 0; ks < 4; ks++) {
                uint32_t qh[4], ql[4];
                ldsm4(qh, qOff + ks * 32);
                ldsm4(ql, qOff + QTILE + ks * 32);
                uint32_t bh[4][4], bl[4][4];
#pragma unroll
                for (int p = 0; p < 4; p++) {
                    ldsm4(bh[p], kOff + p * 16 * AROW + ks * 32);
                    ldsm4(bl[p], kOff + ATILE + p * 16 * AROW + ks * 32);
                }
#pragma unroll
                for (int p = 0; p < 4; p++) {
                    mma_f16(c[2 * p],     qh, bh[p][0], bh[p][1]);
                    mma_f16(c[2 * p + 1], qh, bh[p][2], bh[p][3]);
                }
#pragma unroll
                for (int p = 0; p < 4; p++) {
                    mma_f16(c[2 * p],     qh, bl[p][0], bl[p][1]);
                    mma_f16(c[2 * p + 1], qh, bl[p][2], bl[p][3]);
                }
#pragma unroll
                for (int p = 0; p < 4; p++) {
                    mma_f16(c[2 * p],     ql, bh[p][0], bh[p][1]);
                    mma_f16(c[2 * p + 1], ql, bh[p][2], bh[p][3]);
                }
            }

            // ---- online softmax: max in fp32, p via ex2.approx.f16x2 ----
            float mx0 = -1e30f, mx1 = -1e30f;
#pragma unroll
            for (int j = 0; j < 8; j++) {
                mx0 = fmaxf(mx0, fmaxf(c[j][0], c[j][1]));
                mx1 = fmaxf(mx1, fmaxf(c[j][2], c[j][3]));
            }
            mx0 = fmaxf(mx0, __shfl_xor_sync(0xffffffffu, mx0, 1));
            mx0 = fmaxf(mx0, __shfl_xor_sync(0xffffffffu, mx0, 2));
            mx1 = fmaxf(mx1, __shfl_xor_sync(0xffffffffu, mx1, 1));
            mx1 = fmaxf(mx1, __shfl_xor_sync(0xffffffffu, mx1, 2));
            float mn0 = fmaxf(mm[mt][0], mx0), mn1 = fmaxf(mm[mt][1], mx1);
            float cr0 = exp2f(mm[mt][0] - mn0), cr1 = exp2f(mm[mt][1] - mn1);

            uint32_t p01[8], p23[8];
#pragma unroll
            for (int j = 0; j < 8; j++) {
                p01[j] = ex2_h2(packh2(c[j][0] - mn0, c[j][1] - mn0));
                p23[j] = ex2_h2(packh2(c[j][2] - mn1, c[j][3] - mn1));
            }

#pragma unroll
            for (int j = 0; j < 8; j++) {
                acc[mt][j][0] *= cr0; acc[mt][j][1] *= cr0;
                acc[mt][j][2] *= cr1; acc[mt][j][3] *= cr1;
            }

            // ---- PV + l-sum (ones-column MMA), P and V fp16 ----
            float lsum[4] = {0.f, 0.f, 0.f, 0.f};
#pragma unroll
            for (int ks = 0; ks < 4; ks++) {
                uint32_t ph[4];
                ph[0] = p01[2 * ks];
                ph[1] = p23[2 * ks];
                ph[2] = p01[2 * ks + 1];
                ph[3] = p23[2 * ks + 1];
                mma_f16(lsum, ph, bones, bones);
                uint32_t vh[4][4];
#pragma unroll
                for (int p = 0; p < 4; p++)
                    ldsm4(vh[p], vOff + p * 16 * AROW + ks * 32);
#pragma unroll
                for (int p = 0; p < 4; p++) {
                    mma_f16(acc[mt][2 * p],     ph, vh[p][0], vh[p][1]);
                    mma_f16(acc[mt][2 * p + 1], ph, vh[p][2], vh[p][3]);
                }
            }
            float s0 = __shfl_sync(0xffffffffu, lsum[0], lane & ~3);
            float s1 = __shfl_sync(0xffffffffu, lsum[2], lane & ~3);
            ll[mt][0] = ll[mt][0] * cr0 + s0;
            ll[mt][1] = ll[mt][1] * cr1 + s1;
            mm[mt][0] = mn0; mm[mt][1] = mn1;
        }
    }

    // ---- epilogue: O = acc/l, write single fp16 (lo never consumed) ----
#pragma unroll
    for (int mt = 0; mt < 2; mt++) {
        float i0 = 1.f / ll[mt][0], i1 = 1.f / ll[mt][1];
        size_t rg = qrow0 + wid * 32 + mt * 16 + g;
#pragma unroll
        for (int j = 0; j < 8; j++) {
            int col = h * 64 + j * 8 + 2 * tig;
            *(uint32_t*)(g_Oh + rg * EE + col) =
                packh2(acc[mt][j][0] * i0, acc[mt][j][1] * i0);
            *(uint32_t*)(g_Oh + (rg + 8) * EE + col) =
                packh2(acc[mt][j][2] * i1, acc[mt][j][3] * i1);
        }
    }
}

// ---------------- LayerNorm ----------------
__global__ __launch_bounds__(256) void ln_kernel(
    const float* __restrict__ gamma, const float* __restrict__ beta,
    float* __restrict__ out)
{
    const int row = blockIdx.x;
    const int tid = threadIdx.x;
    const float4 v = *(const float4*)(g_R + (size_t)row * EE + tid * 4);

    float s1 = v.x + v.y + v.z + v.w;
    float s2 = v.x * v.x + v.y * v.y + v.z * v.z + v.w * v.w;

    __shared__ float sh1[8], sh2[8];
#pragma unroll
    for (int off = 16; off > 0; off >>= 1) {
        s1 += __shfl_xor_sync(0xffffffffu, s1, off);
        s2 += __shfl_xor_sync(0xffffffffu, s2, off);
    }
    const int warp = tid >> 5;
    if ((tid & 31) == 0) { sh1[warp] = s1; sh2[warp] = s2; }
    __syncthreads();
    float t1 = 0.f, t2 = 0.f;
#pragma unroll
    for (int w = 0; w < 8; w++) { t1 += sh1[w]; t2 += sh2[w]; }

    const float mean = t1 * (1.0f / EE);
    const float var  = t2 * (1.0f / EE) - mean * mean;
    const float inv  = rsqrtf(var + 1e-6f);

    const float4 gmv = *(const float4*)(gamma + tid * 4);
    const float4 btv = *(const float4*)(beta + tid * 4);
    float4 o;
    o.x = (v.x - mean) * inv * gmv.x + btv.x;
    o.y = (v.y - mean) * inv * gmv.y + btv.y;
    o.z = (v.z - mean) * inv * gmv.z + btv.z;
    o.w = (v.w - mean) * inv * gmv.w + btv.w;
    *(float4*)(out + (size_t)row * EE + tid * 4) = o;
}

// ---------------------------------------------------------------------------
extern "C" void kernel_launch(void* const* d_in, const int* in_sizes, int n_in,
                              void* d_out, int out_size)
{
    const float* X     = (const float*)d_in[0];
    const float* gQ    = (const float*)d_in[1];
    const float* gK    = (const float*)d_in[2];
    const float* Wq    = (const float*)d_in[3];
    const float* Wk    = (const float*)d_in[4];
    const float* Wv    = (const float*)d_in[5];
    const float* Wo    = (const float*)d_in[6];
    const float* gamma = (const float*)d_in[7];
    const float* beta  = (const float*)d_in[8];
    float* out = (float*)d_out;

    cudaFuncSetAttribute(gemm_kernel,
                         cudaFuncAttributeMaxDynamicSharedMemorySize, GEMM_SMEM);
    cudaFuncSetAttribute(attn_kernel,
                         cudaFuncAttributeMaxDynamicSharedMemorySize, ATTN_SMEM);

    prep_x_kernel<<<NELEM / 1024, 256>>>(X);
    prep_w_kernel<<<dim3(32, 32, 4), dim3(32, 8)>>>(Wq, Wk, Wv, Wo);

    gemm_kernel<<<dim3(8, 64, 3), 128, GEMM_SMEM>>>(gQ, gK, X, 0);

    attn_kernel<<<dim3(8, HH, BB), 128, ATTN_SMEM>>>();

    gemm_kernel<<<dim3(8, 64, 1), 128, GEMM_SMEM>>>(gQ, gK, X, 3);
    ln_kernel<<<M_TOT, 256>>>(gamma, beta, out);
}